// round 13
// baseline (speedup 1.0000x reference)
#include <cuda_runtime.h>
#include <cuda_bf16.h>
#include <cstdint>

// Problem constants: B=16, T=64, N=512, H=128, P=12
#define NB   512
#define BB   16
#define TT   64
#define HH   128
#define PP   12
#define RWS  (NB*BB)          // 8192 rows (n,b)
#define BH   (BB*HH)          // 2048

// Scratch (device globals; no allocation allowed)
__device__ float g_U   [RWS*HH];          // update gate, h-layout
__device__ float g_XAGG[TT*BB*NB];        // [t][b][m] = (L @ x_t)[b,m]
__device__ float g_HS1 [BB*TT*NB];        // [b][t][n]
__device__ float g_BETA[BB*TT];
__device__ __nv_bfloat16 g_Lh  [NB*NB];   // L hi/lo (A of big GEMM)
__device__ __nv_bfloat16 g_Ll  [NB*NB];
__device__ __nv_bfloat16 g_Hh  [RWS*HH];  // H hi/lo
__device__ __nv_bfloat16 g_Hl  [RWS*HH];
__device__ __nv_bfloat16 g_RHh [RWS*HH];  // (r*h) hi/lo
__device__ __nv_bfloat16 g_RHl [RWS*HH];
__device__ __nv_bfloat16 g_AGGh[RWS*HH];  // L@B result hi/lo
__device__ __nv_bfloat16 g_AGGl[RWS*HH];
__device__ __nv_bfloat16 g_W1hh[HH*2*HH]; // W1 rows 1..128 hi/lo [128][256]
__device__ __nv_bfloat16 g_W1hl[HH*2*HH];
__device__ __nv_bfloat16 g_W2hh[HH*HH];   // W2 rows 1..128 hi/lo [128][128]
__device__ __nv_bfloat16 g_W2hl[HH*HH];

// ---------------------------------------------------------------------------
// Helpers
// ---------------------------------------------------------------------------
__device__ __forceinline__ uint32_t smem_to_u32(const void* p) {
    uint32_t a;
    asm("{ .reg .u64 t; cvta.to.shared.u64 t, %1; cvt.u32.u64 %0, t; }" : "=r"(a) : "l"(p));
    return a;
}
__device__ __forceinline__ void cp16(uint32_t saddr, const void* gaddr) {
    asm volatile("cp.async.cg.shared.global [%0], [%1], 16;" :: "r"(saddr), "l"(gaddr));
}
__device__ __forceinline__ void cp_commit() {
    asm volatile("cp.async.commit_group;" ::: "memory");
}
__device__ __forceinline__ void ldsm4(uint32_t r[4], uint32_t addr) {
    asm volatile("ldmatrix.sync.aligned.m8n8.x4.shared.b16 {%0,%1,%2,%3}, [%4];"
                 : "=r"(r[0]), "=r"(r[1]), "=r"(r[2]), "=r"(r[3]) : "r"(addr));
}
__device__ __forceinline__ void ldsm4t(uint32_t r[4], uint32_t addr) {
    asm volatile("ldmatrix.sync.aligned.m8n8.x4.trans.shared.b16 {%0,%1,%2,%3}, [%4];"
                 : "=r"(r[0]), "=r"(r[1]), "=r"(r[2]), "=r"(r[3]) : "r"(addr));
}
__device__ __forceinline__ void mma_bf16(float d[4], const uint32_t a[4],
                                         uint32_t b0, uint32_t b1) {
    asm volatile(
        "mma.sync.aligned.m16n8k16.row.col.f32.bf16.bf16.f32 "
        "{%0,%1,%2,%3}, {%4,%5,%6,%7}, {%8,%9}, {%0,%1,%2,%3};"
        : "+f"(d[0]), "+f"(d[1]), "+f"(d[2]), "+f"(d[3])
        : "r"(a[0]), "r"(a[1]), "r"(a[2]), "r"(a[3]), "r"(b0), "r"(b1));
}
__device__ __forceinline__ void split_bf16(float v, __nv_bfloat16& hi, __nv_bfloat16& lo) {
    hi = __float2bfloat16(v);
    lo = __float2bfloat16(v - __bfloat162float(hi));
}
__device__ __forceinline__ float sigmoid_fast(float x) {
    return __fdividef(1.f, 1.f + __expf(-x));
}
__device__ __forceinline__ float tanh_exp(float x) {
    // tanh(x) = 1 - 2/(e^{2x}+1); MUFU + fast div, few-ulp, stable both tails
    return 1.f - __fdividef(2.f, __expf(2.f * x) + 1.f);
}

// ---------------------------------------------------------------------------
// Big tensor GEMM: C[512][2048] = A[512,512] @ B[512,2048] via 3-pass bf16 split.
// CTA tile 64m x 128n, grid (16, 8), 256 threads (8 warps = 4m x 2n).
// Output written as bf16 hi/lo pair (Ch, Cl).
// ---------------------------------------------------------------------------
#define STAGE_BYTES 24576
#define OFF_AH 0
#define OFF_AL 4096
#define OFF_BH 8192
#define OFF_BL 16384
#define SM_TMMA (2*STAGE_BYTES)     // 49152

__global__ __launch_bounds__(256) void k_tmma(
    const __nv_bfloat16* __restrict__ Ah, const __nv_bfloat16* __restrict__ Al,
    const __nv_bfloat16* __restrict__ Bh, const __nv_bfloat16* __restrict__ Bl,
    __nv_bfloat16* __restrict__ Ch, __nv_bfloat16* __restrict__ Cl)
{
    extern __shared__ char smc[];
    const uint32_t sbase = smem_to_u32(smc);
    const int tid = threadIdx.x, wid = tid >> 5, lane = tid & 31;
    const int m0c = blockIdx.y * 64;
    const int n0c = blockIdx.x * 128;
    const int mw = (wid & 3) * 16;
    const int nw = (wid >> 2) * 64;

    float acc[8][4];
#pragma unroll
    for (int i = 0; i < 8; i++)
#pragma unroll
        for (int j = 0; j < 4; j++) acc[i][j] = 0.f;

    const int am = tid >> 2, aseg = tid & 3;
    const uint32_t aso = (uint32_t)(am * 64 + ((aseg ^ (am & 3)) << 4));

#define LOAD_STAGE(s) do {                                                         \
    const int kk = (s) * 32;                                                       \
    const uint32_t sb = sbase + ((s) & 1) * STAGE_BYTES;                           \
    cp16(sb + OFF_AH + aso, &Ah[(m0c + am) * 512 + kk + aseg * 8]);                \
    cp16(sb + OFF_AL + aso, &Al[(m0c + am) * 512 + kk + aseg * 8]);                \
    _Pragma("unroll")                                                              \
    for (int u = 0; u < 2; u++) {                                                  \
        const int unit = tid + u * 256;                                            \
        const int bk = unit >> 4, bs = unit & 15;                                  \
        const uint32_t bso = (uint32_t)(bk * 256 + ((bs ^ (bk & 7)) << 4));        \
        cp16(sb + OFF_BH + bso, &Bh[(kk + bk) * 2048 + n0c + bs * 8]);             \
        cp16(sb + OFF_BL + bso, &Bl[(kk + bk) * 2048 + n0c + bs * 8]);             \
    }                                                                              \
    cp_commit();                                                                   \
} while (0)

    LOAD_STAGE(0);
    LOAD_STAGE(1);

    for (int s = 0; s < 16; s++) {
        if (s < 14) asm volatile("cp.async.wait_group 1;" ::: "memory");
        else        asm volatile("cp.async.wait_group 0;" ::: "memory");
        __syncthreads();

        const uint32_t sb = sbase + (s & 1) * STAGE_BYTES;
#pragma unroll
        for (int kh = 0; kh < 32; kh += 16) {
            uint32_t afh[4], afl[4];
            {
                const int row = mw + (lane & 15);
                const int seg = (kh >> 3) + (lane >> 4);
                const uint32_t ad = sb + OFF_AH + row * 64 + ((seg ^ (row & 3)) << 4);
                ldsm4(afh, ad);
                ldsm4(afl, ad + (OFF_AL - OFF_AH));
            }
            uint32_t bfh[4][4], bfl[4][4];
            {
                const int bk = kh + (lane & 15);
#pragma unroll
                for (int g = 0; g < 4; g++) {
                    const int seg = (nw >> 3) + 2 * g + (lane >> 4);
                    const uint32_t bd = sb + OFF_BH + bk * 256 + ((seg ^ (bk & 7)) << 4);
                    ldsm4t(bfh[g], bd);
                    ldsm4t(bfl[g], bd + (OFF_BL - OFF_BH));
                }
            }
#pragma unroll
            for (int nf = 0; nf < 8; nf++) {
                const int g = nf >> 1, h = (nf & 1) * 2;
                mma_bf16(acc[nf], afh, bfh[g][h], bfh[g][h + 1]);
                mma_bf16(acc[nf], afh, bfl[g][h], bfl[g][h + 1]);
                mma_bf16(acc[nf], afl, bfh[g][h], bfh[g][h + 1]);
            }
        }
        __syncthreads();
        if (s + 2 < 16) LOAD_STAGE(s + 2);
    }
#undef LOAD_STAGE

    const int r0 = m0c + mw + (lane >> 2);
    const int cb = n0c + nw + (lane & 3) * 2;
#pragma unroll
    for (int nf = 0; nf < 8; nf++) {
        const int col = cb + nf * 8;
#pragma unroll
        for (int half = 0; half < 2; half++) {
            const int r = r0 + half * 8;
            const int idx = r * BH + col;
            __nv_bfloat16 h0, l0, h1, l1;
            split_bf16(acc[nf][half * 2 + 0], h0, l0);
            split_bf16(acc[nf][half * 2 + 1], h1, l1);
            __nv_bfloat162 ph; ph.x = h0; ph.y = h1;
            __nv_bfloat162 pl; pl.x = l0; pl.y = l1;
            *reinterpret_cast<__nv_bfloat162*>(&Ch[idx]) = ph;
            *reinterpret_cast<__nv_bfloat162*>(&Cl[idx]) = pl;
        }
    }
}

// ---------------------------------------------------------------------------
// Gate (tensorized, single-wave): sigmoid(AGG @ W1h + xagg*W1x + b1).
// ONE CTA handles both o-tiles (o in [0,256)) sequentially to keep grid at
// 128 CTAs = 1 wave on 148 SMs. smem 160KB: A 32KB + full W1 hi/lo 128KB.
//   AH 0 (16KB), AL 16384, WH 32768 (64KB), WL 98304 (64KB).
// grid (1, 128), 256 threads (8 warps = 4m x 2n; warp n-tile 128 of 256).
// ---------------------------------------------------------------------------
#define SM_GATE 163840

__global__ __launch_bounds__(256) void k_gate_t(
    const __nv_bfloat16* __restrict__ AGGh, const __nv_bfloat16* __restrict__ AGGl,
    const __nv_bfloat16* __restrict__ W1hh, const __nv_bfloat16* __restrict__ W1hl,
    const float* __restrict__ W1, const float* __restrict__ b1,
    const float* __restrict__ Xagg, int t,
    const __nv_bfloat16* __restrict__ Hh, const __nv_bfloat16* __restrict__ Hl,
    __nv_bfloat16* __restrict__ RHh, __nv_bfloat16* __restrict__ RHl,
    float* __restrict__ U)
{
    extern __shared__ char smc[];
    const uint32_t sbase = smem_to_u32(smc);
    const int tid = threadIdx.x, wid = tid >> 5, lane = tid & 31;
    const int mw = (wid & 3) * 16;
    const int nw2 = (wid >> 2) * 128;       // warp n-offset within 256
    const int r0c = blockIdx.y * 64;

    // Load A tile (64 x 128 bf16 hi/lo, 256B rows, swizzled)
#pragma unroll
    for (int u = 0; u < 4; u++) {
        const int unit = tid + u * 256;
        const int row = unit >> 4, seg = unit & 15;
        const uint32_t so = (uint32_t)(row * 256 + ((seg ^ (row & 7)) << 4));
        cp16(sbase + 0     + so, AGGh + (r0c + row) * 128 + seg * 8);
        cp16(sbase + 16384 + so, AGGl + (r0c + row) * 128 + seg * 8);
    }
    // Load full W1 (128 x 256 bf16 hi/lo, 512B rows, swizzled)
#pragma unroll
    for (int u = 0; u < 16; u++) {
        const int unit = tid + u * 256;
        const int k = unit >> 5, seg = unit & 31;
        const uint32_t so = (uint32_t)(k * 512 + ((seg ^ (k & 7)) << 4));
        cp16(sbase + 32768 + so, W1hh + k * 256 + seg * 8);
        cp16(sbase + 98304 + so, W1hl + k * 256 + seg * 8);
    }
    cp_commit();
    asm volatile("cp.async.wait_group 0;" ::: "memory");
    __syncthreads();

    const int rr0 = r0c + mw + (lane >> 2);

#pragma unroll
    for (int oh = 0; oh < 2; oh++) {
        float acc[8][4];
#pragma unroll
        for (int i = 0; i < 8; i++)
#pragma unroll
            for (int j = 0; j < 4; j++) acc[i][j] = 0.f;

#pragma unroll
        for (int kh = 0; kh < 8; kh++) {
            uint32_t afh[4], afl[4];
            {
                const int row = mw + (lane & 15);
                const int seg = kh * 2 + (lane >> 4);
                const uint32_t ao = (uint32_t)(row * 256 + ((seg ^ (row & 7)) << 4));
                ldsm4(afh, sbase + ao);
                ldsm4(afl, sbase + 16384 + ao);
            }
            uint32_t bfh[4][4], bfl[4][4];
            {
                const int bk = kh * 16 + (lane & 15);
#pragma unroll
                for (int g = 0; g < 4; g++) {
                    const int seg = (nw2 >> 3) + oh * 8 + 2 * g + (lane >> 4);
                    const uint32_t wo = (uint32_t)(bk * 512 + ((seg ^ (bk & 7)) << 4));
                    ldsm4t(bfh[g], sbase + 32768 + wo);
                    ldsm4t(bfl[g], sbase + 98304 + wo);
                }
            }
#pragma unroll
            for (int nf = 0; nf < 8; nf++) {
                const int g = nf >> 1, h = (nf & 1) * 2;
                mma_bf16(acc[nf], afh, bfh[g][h], bfh[g][h + 1]);
                mma_bf16(acc[nf], afh, bfl[g][h], bfl[g][h + 1]);
                mma_bf16(acc[nf], afl, bfh[g][h], bfh[g][h + 1]);
            }
        }

        // Epilogue for this o-half.
#pragma unroll
        for (int half = 0; half < 2; half++) {
            const int r = rr0 + half * 8;
            const int mq = r >> 4, b = r & 15;
            const float xa = Xagg[t * (BB * NB) + b * NB + mq];
            const bool isR = (mq < 256);
#pragma unroll
            for (int nf = 0; nf < 8; nf++) {
                const int o = nw2 + oh * 64 + nf * 8 + (lane & 3) * 2;
                const float v0 = acc[nf][half * 2 + 0] + xa * W1[o]     + b1[o];
                const float v1 = acc[nf][half * 2 + 1] + xa * W1[o + 1] + b1[o + 1];
                const float s0 = sigmoid_fast(v0);
                const float s1 = sigmoid_fast(v1);
                const int bit = (o >= 128);
                const int c = o & 127;
                if (isR) {
                    const int n = 2 * mq + bit;
                    const int idx = (n * 16 + b) * 128 + c;
                    __nv_bfloat162 hh = *reinterpret_cast<const __nv_bfloat162*>(&Hh[idx]);
                    __nv_bfloat162 hl = *reinterpret_cast<const __nv_bfloat162*>(&Hl[idx]);
                    const float h0 = __bfloat162float(hh.x) + __bfloat162float(hl.x);
                    const float h1 = __bfloat162float(hh.y) + __bfloat162float(hl.y);
                    __nv_bfloat16 a0, c0, a1, c1;
                    split_bf16(s0 * h0, a0, c0);
                    split_bf16(s1 * h1, a1, c1);
                    __nv_bfloat162 ph; ph.x = a0; ph.y = a1;
                    __nv_bfloat162 pl; pl.x = c0; pl.y = c1;
                    *reinterpret_cast<__nv_bfloat162*>(&RHh[idx]) = ph;
                    *reinterpret_cast<__nv_bfloat162*>(&RHl[idx]) = pl;
                } else {
                    const int nbase = 2 * (mq - 256) + bit;
                    const int idx = (nbase * 16 + b) * 128 + c;
                    *reinterpret_cast<float2*>(&U[idx]) = make_float2(s0, s1);
                }
            }
        }
    }
}

// ---------------------------------------------------------------------------
// K=128 HMMA core for cand: A[64 rows x 128] (hi/lo) @ W[128 x 128] (hi/lo),
// 3-pass. 256 threads, 8 warps (4m x 2n). Single-shot smem:
// AH 0 (16KB), AL 16384, WH 32768 (32KB), WL 65536 -> 96KB
// ---------------------------------------------------------------------------
#define SM_GC 98304

template<int LDW>
__device__ __forceinline__ void hmma_k128(
    const __nv_bfloat16* __restrict__ Ah_g,  // &A[r0c*128]
    const __nv_bfloat16* __restrict__ Al_g,
    const __nv_bfloat16* __restrict__ Wh_g,  // &W[o0], row stride LDW
    const __nv_bfloat16* __restrict__ Wl_g,
    uint32_t sbase, float acc[8][4], int mw, int nw, int lane, int tid)
{
#pragma unroll
    for (int u = 0; u < 4; u++) {
        const int unit = tid + u * 256;
        const int row = unit >> 4, seg = unit & 15;
        const uint32_t so = (uint32_t)(row * 256 + ((seg ^ (row & 7)) << 4));
        cp16(sbase + 0     + so, Ah_g + row * 128 + seg * 8);
        cp16(sbase + 16384 + so, Al_g + row * 128 + seg * 8);
    }
#pragma unroll
    for (int u = 0; u < 8; u++) {
        const int unit = tid + u * 256;
        const int k = unit >> 4, seg = unit & 15;
        const uint32_t so = (uint32_t)(k * 256 + ((seg ^ (k & 7)) << 4));
        cp16(sbase + 32768 + so, Wh_g + k * LDW + seg * 8);
        cp16(sbase + 65536 + so, Wl_g + k * LDW + seg * 8);
    }
    cp_commit();
    asm volatile("cp.async.wait_group 0;" ::: "memory");
    __syncthreads();

#pragma unroll
    for (int kh = 0; kh < 8; kh++) {
        uint32_t afh[4], afl[4];
        {
            const int row = mw + (lane & 15);
            const int seg = kh * 2 + (lane >> 4);
            const uint32_t ao = (uint32_t)(row * 256 + ((seg ^ (row & 7)) << 4));
            ldsm4(afh, sbase + ao);
            ldsm4(afl, sbase + 16384 + ao);
        }
        uint32_t bfh[4][4], bfl[4][4];
        {
            const int bk = kh * 16 + (lane & 15);
#pragma unroll
            for (int g = 0; g < 4; g++) {
                const int seg = (nw >> 3) + 2 * g + (lane >> 4);
                const uint32_t wo = (uint32_t)(bk * 256 + ((seg ^ (bk & 7)) << 4));
                ldsm4t(bfh[g], sbase + 32768 + wo);
                ldsm4t(bfl[g], sbase + 65536 + wo);
            }
        }
#pragma unroll
        for (int nf = 0; nf < 8; nf++) {
            const int g = nf >> 1, h = (nf & 1) * 2;
            mma_bf16(acc[nf], afh, bfh[g][h], bfh[g][h + 1]);
            mma_bf16(acc[nf], afh, bfl[g][h], bfl[g][h + 1]);
            mma_bf16(acc[nf], afl, bfh[g][h], bfh[g][h + 1]);
        }
    }
}

// ---------------------------------------------------------------------------
// Candidate (tensorized): C = tanh(AGG2 @ W2h + xagg*W2x + b2);
// h_new = u*h + (1-u)*C; write Hh/Hl; fused hs1 row-reduction.
// grid (1, 128), 256 threads.
// ---------------------------------------------------------------------------
__global__ __launch_bounds__(256) void k_cand_t(
    const __nv_bfloat16* __restrict__ AGGh, const __nv_bfloat16* __restrict__ AGGl,
    const __nv_bfloat16* __restrict__ W2hh, const __nv_bfloat16* __restrict__ W2hl,
    const float* __restrict__ W2, const float* __restrict__ b2,
    const float* __restrict__ Xagg, int t,
    const float* __restrict__ aw1, const float* __restrict__ ab1,
    const float* __restrict__ U,
    __nv_bfloat16* __restrict__ Hh, __nv_bfloat16* __restrict__ Hl,
    float* __restrict__ HS1)
{
    extern __shared__ char smc[];
    __shared__ float sRed[64];
    const uint32_t sbase = smem_to_u32(smc);
    const int tid = threadIdx.x, wid = tid >> 5, lane = tid & 31;
    const int mw = (wid & 3) * 16, nw = (wid >> 2) * 64;
    const int r0c = blockIdx.y * 64;

    float acc[8][4];
#pragma unroll
    for (int i = 0; i < 8; i++)
#pragma unroll
        for (int j = 0; j < 4; j++) acc[i][j] = 0.f;

    hmma_k128<128>(AGGh + r0c * 128, AGGl + r0c * 128, W2hh, W2hl,
                   sbase, acc, mw, nw, lane, tid);

    const int rr0 = r0c + mw + (lane >> 2);
    float part[2] = {0.f, 0.f};
#pragma unroll
    for (int half = 0; half < 2; half++) {
        const int r = rr0 + half * 8;
        const int mq = r >> 4, b = r & 15;
        const float xa = Xagg[t * (BB * NB) + b * NB + mq];
#pragma unroll
        for (int nf = 0; nf < 8; nf++) {
            const int o = nw + (lane & 3) * 2 + nf * 8;
            const float pre0 = acc[nf][half * 2 + 0] + xa * W2[o]     + b2[o];
            const float pre1 = acc[nf][half * 2 + 1] + xa * W2[o + 1] + b2[o + 1];
            const float cv0 = tanh_exp(pre0);
            const float cv1 = tanh_exp(pre1);
            const int idx = r * 128 + o;
            const float2 uu = *reinterpret_cast<const float2*>(&U[idx]);
            __nv_bfloat162 hh = *reinterpret_cast<const __nv_bfloat162*>(&Hh[idx]);
            __nv_bfloat162 hl = *reinterpret_cast<const __nv_bfloat162*>(&Hl[idx]);
            const float h0 = __bfloat162float(hh.x) + __bfloat162float(hl.x);
            const float h1 = __bfloat162float(hh.y) + __bfloat162float(hl.y);
            const float hn0 = uu.x * h0 + (1.f - uu.x) * cv0;
            const float hn1 = uu.y * h1 + (1.f - uu.y) * cv1;
            __nv_bfloat16 a0, c0, a1, c1;
            split_bf16(hn0, a0, c0);
            split_bf16(hn1, a1, c1);
            __nv_bfloat162 ph; ph.x = a0; ph.y = a1;
            __nv_bfloat162 pl; pl.x = c0; pl.y = c1;
            *reinterpret_cast<__nv_bfloat162*>(&Hh[idx]) = ph;
            *reinterpret_cast<__nv_bfloat162*>(&Hl[idx]) = pl;
            part[half] += hn0 * aw1[o] + hn1 * aw1[o + 1];
        }
    }
    // reduce over the 4 lanes of each quad (same row)
#pragma unroll
    for (int half = 0; half < 2; half++) {
        part[half] += __shfl_xor_sync(0xffffffffu, part[half], 1);
        part[half] += __shfl_xor_sync(0xffffffffu, part[half], 2);
    }
    if (wid >= 4 && (lane & 3) == 0) {
        sRed[mw + (lane >> 2)]     = part[0];
        sRed[mw + 8 + (lane >> 2)] = part[1];
    }
    __syncthreads();
    if (wid < 4 && (lane & 3) == 0) {
        const float abv = ab1[0];
#pragma unroll
        for (int half = 0; half < 2; half++) {
            const int lr = mw + half * 8 + (lane >> 2);
            const int r = r0c + lr;
            const int mq = r >> 4, b = r & 15;
            HS1[b * (TT * NB) + t * NB + mq] = part[half] + sRed[lr] + abv;
        }
    }
}

// ---------------------------------------------------------------------------
// One-time splits
// ---------------------------------------------------------------------------
__global__ void k_splitL(const float* __restrict__ L,
                         __nv_bfloat16* __restrict__ Lh, __nv_bfloat16* __restrict__ Ll)
{
    int i = blockIdx.x * 512 + threadIdx.x;
    __nv_bfloat16 hi, lo;
    split_bf16(L[i], hi, lo);
    Lh[i] = hi; Ll[i] = lo;
}

__global__ void k_splitW(const float* __restrict__ W1, const float* __restrict__ W2,
                         __nv_bfloat16* __restrict__ W1h, __nv_bfloat16* __restrict__ W1l,
                         __nv_bfloat16* __restrict__ W2h, __nv_bfloat16* __restrict__ W2l)
{
    int i = blockIdx.x * 256 + threadIdx.x;
    __nv_bfloat16 hi, lo;
    if (i < 128 * 256) {
        split_bf16(W1[256 + i], hi, lo);   // skip row 0 (x weight)
        W1h[i] = hi; W1l[i] = lo;
    } else {
        int j = i - 128 * 256;
        split_bf16(W2[128 + j], hi, lo);   // skip row 0
        W2h[j] = hi; W2l[j] = lo;
    }
}

// ---------------------------------------------------------------------------
// XAGG precompute (runs once; not hot)
// ---------------------------------------------------------------------------
__global__ __launch_bounds__(256) void k_xagg(
    const float* __restrict__ X, const float* __restrict__ L, float* __restrict__ XAGG)
{
    __shared__ float As[16][64];
    __shared__ float Bs[16][64];
    const int tid = threadIdx.x;
    const int tx = tid & 15, ty = tid >> 4;
    const int r0 = blockIdx.y * 64;
    const int m0 = blockIdx.x * 64;

    float acc[4][4];
#pragma unroll
    for (int i = 0; i < 4; i++)
#pragma unroll
        for (int j = 0; j < 4; j++) acc[i][j] = 0.f;

    const int row = tid >> 2;
    const int kq  = (tid & 3) * 4;

    for (int k0 = 0; k0 < 512; k0 += 16) {
        float4 av = *reinterpret_cast<const float4*>(&X[(r0 + row) * 512 + k0 + kq]);
        As[kq + 0][row] = av.x; As[kq + 1][row] = av.y;
        As[kq + 2][row] = av.z; As[kq + 3][row] = av.w;
        float4 bv = *reinterpret_cast<const float4*>(&L[(m0 + row) * 512 + k0 + kq]);
        Bs[kq + 0][row] = bv.x; Bs[kq + 1][row] = bv.y;
        Bs[kq + 2][row] = bv.z; Bs[kq + 3][row] = bv.w;
        __syncthreads();
#pragma unroll
        for (int k = 0; k < 16; k++) {
            float4 a4 = *reinterpret_cast<const float4*>(&As[k][ty * 4]);
            float4 b4 = *reinterpret_cast<const float4*>(&Bs[k][tx * 4]);
            float a_[4] = {a4.x, a4.y, a4.z, a4.w};
            float b_[4] = {b4.x, b4.y, b4.z, b4.w};
#pragma unroll
            for (int i = 0; i < 4; i++)
#pragma unroll
                for (int j = 0; j < 4; j++)
                    acc[i][j] += a_[i] * b_[j];
        }
        __syncthreads();
    }
#pragma unroll
    for (int i = 0; i < 4; i++) {
        int bt = r0 + ty * 4 + i;
        int b = bt >> 6, tt = bt & 63;
#pragma unroll
        for (int j = 0; j < 4; j++)
            XAGG[tt * (BB * NB) + b * NB + m0 + tx * 4 + j] = acc[i][j];
    }
}

// ---------------------------------------------------------------------------
// Attention f,g + softmax beta per batch. grid 16, 256 thr.
// ---------------------------------------------------------------------------
__global__ void k_fg(const float* __restrict__ HS1,
                     const float* __restrict__ w2, const float* __restrict__ w3,
                     const float* __restrict__ b2p, const float* __restrict__ b3p,
                     float* __restrict__ BETA)
{
    __shared__ float sf[64], sg[64], st[64];
    const int b = blockIdx.x, tid = threadIdx.x;
    const int w = tid >> 5, lane = tid & 31;
    for (int t = w; t < 64; t += 8) {
        float fs = 0.f, gs = 0.f;
        for (int n = lane; n < 512; n += 32) {
            float v = HS1[b * (TT * NB) + t * NB + n];
            fs += v * w2[n];
            gs += v * w3[n];
        }
#pragma unroll
        for (int off = 16; off; off >>= 1) {
            fs += __shfl_down_sync(0xffffffffu, fs, off);
            gs += __shfl_down_sync(0xffffffffu, gs, off);
        }
        if (lane == 0) { sf[t] = fs + b2p[0]; sg[t] = gs + b3p[0]; }
    }
    __syncthreads();
    if (tid == 0) {
        float mx = -1e30f;
        for (int t = 0; t < 64; t++) { st[t] = sf[t] * sg[t]; mx = fmaxf(mx, st[t]); }
        float sum = 0.f;
        for (int t = 0; t < 64; t++) { st[t] = expf(st[t] - mx); sum += st[t]; }
        float inv = 1.f / sum;
        for (int t = 0; t < 64; t++) BETA[b * 64 + t] = st[t] * inv;
    }
}

// ---------------------------------------------------------------------------
// Output: out[b,p,n] = sum_t beta[b,t]*hs1[b,t,n]*W_out[t,p] + b_out[p]
// ---------------------------------------------------------------------------
__global__ void k_out(const float* __restrict__ HS1, const float* __restrict__ BETA,
                      const float* __restrict__ Wout, const float* __restrict__ bout,
                      float* __restrict__ out)
{
    const int idx = blockIdx.x * 256 + threadIdx.x;
    const int b = idx >> 9, n = idx & 511;
    float acc[PP];
#pragma unroll
    for (int p = 0; p < PP; p++) acc[p] = 0.f;
    for (int t = 0; t < 64; t++) {
        float v = BETA[b * 64 + t] * HS1[b * (TT * NB) + t * NB + n];
#pragma unroll
        for (int p = 0; p < PP; p++) acc[p] += v * Wout[t * PP + p];
    }
#pragma unroll
    for (int p = 0; p < PP; p++)
        out[b * (PP * NB) + p * NB + n] = acc[p] + bout[p];
}

// ---------------------------------------------------------------------------
extern "C" void kernel_launch(void* const* d_in, const int* in_sizes, int n_in,
                              void* d_out, int out_size)
{
    (void)in_sizes; (void)n_in; (void)out_size;
    const float* X    = (const float*)d_in[0];
    const float* L    = (const float*)d_in[1];
    const float* W1   = (const float*)d_in[2];
    const float* b1   = (const float*)d_in[3];
    const float* W2   = (const float*)d_in[4];
    const float* b2   = (const float*)d_in[5];
    const float* aw1  = (const float*)d_in[6];
    const float* aw2  = (const float*)d_in[7];
    const float* aw3  = (const float*)d_in[8];
    const float* ab1  = (const float*)d_in[9];
    const float* ab2  = (const float*)d_in[10];
    const float* ab3  = (const float*)d_in[11];
    const float* Wout = (const float*)d_in[12];
    const float* bout = (const float*)d_in[13];
    float* out = (float*)d_out;

    float *U, *XA, *HS1, *BETA;
    __nv_bfloat16 *Lh, *Ll, *Hh, *Hl, *RHh, *RHl, *AGGh, *AGGl;
    __nv_bfloat16 *W1hh, *W1hl, *W2hh, *W2hl;
    cudaGetSymbolAddress((void**)&U,    g_U);
    cudaGetSymbolAddress((void**)&XA,   g_XAGG);
    cudaGetSymbolAddress((void**)&HS1,  g_HS1);
    cudaGetSymbolAddress((void**)&BETA, g_BETA);
    cudaGetSymbolAddress((void**)&Lh,   g_Lh);
    cudaGetSymbolAddress((void**)&Ll,   g_Ll);
    cudaGetSymbolAddress((void**)&Hh,   g_Hh);
    cudaGetSymbolAddress((void**)&Hl,   g_Hl);
    cudaGetSymbolAddress((void**)&RHh,  g_RHh);
    cudaGetSymbolAddress((void**)&RHl,  g_RHl);
    cudaGetSymbolAddress((void**)&AGGh, g_AGGh);
    cudaGetSymbolAddress((void**)&AGGl, g_AGGl);
    cudaGetSymbolAddress((void**)&W1hh, g_W1hh);
    cudaGetSymbolAddress((void**)&W1hl, g_W1hl);
    cudaGetSymbolAddress((void**)&W2hh, g_W2hh);
    cudaGetSymbolAddress((void**)&W2hl, g_W2hl);

    cudaFuncSetAttribute(k_tmma,   cudaFuncAttributeMaxDynamicSharedMemorySize, SM_TMMA);
    cudaFuncSetAttribute(k_gate_t, cudaFuncAttributeMaxDynamicSharedMemorySize, SM_GATE);
    cudaFuncSetAttribute(k_cand_t, cudaFuncAttributeMaxDynamicSharedMemorySize, SM_GC);

    cudaMemsetAsync(Hh,   0, sizeof(__nv_bfloat16) * RWS * HH);
    cudaMemsetAsync(Hl,   0, sizeof(__nv_bfloat16) * RWS * HH);
    cudaMemsetAsync(AGGh, 0, sizeof(__nv_bfloat16) * RWS * HH);
    cudaMemsetAsync(AGGl, 0, sizeof(__nv_bfloat16) * RWS * HH);

    k_splitL<<<512, 512>>>(L, Lh, Ll);
    k_splitW<<<192, 256>>>(W1, W2, W1hh, W1hl, W2hh, W2hl);
    k_xagg<<<dim3(8, 16), 256>>>(X, L, XA);

    for (int t = 0; t < TT; t++) {
        if (t) k_tmma<<<dim3(16, 8), 256, SM_TMMA>>>(Lh, Ll, Hh, Hl, AGGh, AGGl);
        k_gate_t<<<dim3(1, 128), 256, SM_GATE>>>(AGGh, AGGl, W1hh, W1hl, W1, b1,
                                                 XA, t, Hh, Hl, RHh, RHl, U);
        if (t) k_tmma<<<dim3(16, 8), 256, SM_TMMA>>>(Lh, Ll, RHh, RHl, AGGh, AGGl);
        k_cand_t<<<dim3(1, 128), 256, SM_GC>>>(AGGh, AGGl, W2hh, W2hl, W2, b2,
                                               XA, t, aw1, ab1, U, Hh, Hl, HS1);
    }

    k_fg<<<16, 256>>>(HS1, aw2, aw3, ab2, ab3, BETA);
    k_out<<<32, 256>>>(HS1, BETA, Wout, bout, out);
}

// round 14
// speedup vs baseline: 1.1779x; 1.1779x over previous
#include <cuda_runtime.h>
#include <cuda_bf16.h>
#include <cstdint>

// Problem constants: B=16, T=64, N=512, H=128, P=12
#define NB   512
#define BB   16
#define TT   64
#define HH   128
#define PP   12
#define RWS  (NB*BB)          // 8192 rows (n,b)
#define BH   (BB*HH)          // 2048

// Scratch (device globals; no allocation allowed)
__device__ float g_U   [RWS*HH];          // update gate, h-layout
__device__ float g_XAGG[TT*BB*NB];        // [t][b][m] = (L @ x_t)[b,m]
__device__ float g_HS1 [BB*TT*NB];        // [b][t][n]
__device__ float g_BETA[BB*TT];
__device__ __nv_bfloat16 g_Lh  [NB*NB];   // L hi/lo (A of big GEMM)
__device__ __nv_bfloat16 g_Ll  [NB*NB];
__device__ __nv_bfloat16 g_Hh  [RWS*HH];  // H hi/lo
__device__ __nv_bfloat16 g_Hl  [RWS*HH];
__device__ __nv_bfloat16 g_RHh [RWS*HH];  // (r*h) hi/lo
__device__ __nv_bfloat16 g_RHl [RWS*HH];
__device__ __nv_bfloat16 g_AGGh[RWS*HH];  // L@B result hi/lo
__device__ __nv_bfloat16 g_AGGl[RWS*HH];
__device__ __nv_bfloat16 g_W1hh[HH*2*HH]; // W1 rows 1..128 hi/lo [128][256]
__device__ __nv_bfloat16 g_W1hl[HH*2*HH];
__device__ __nv_bfloat16 g_W2hh[HH*HH];   // W2 rows 1..128 hi/lo [128][128]
__device__ __nv_bfloat16 g_W2hl[HH*HH];

// ---------------------------------------------------------------------------
// Helpers
// ---------------------------------------------------------------------------
__device__ __forceinline__ uint32_t smem_to_u32(const void* p) {
    uint32_t a;
    asm("{ .reg .u64 t; cvta.to.shared.u64 t, %1; cvt.u32.u64 %0, t; }" : "=r"(a) : "l"(p));
    return a;
}
__device__ __forceinline__ void cp16(uint32_t saddr, const void* gaddr) {
    asm volatile("cp.async.cg.shared.global [%0], [%1], 16;" :: "r"(saddr), "l"(gaddr));
}
__device__ __forceinline__ void cp_commit() {
    asm volatile("cp.async.commit_group;" ::: "memory");
}
__device__ __forceinline__ void ldsm4(uint32_t r[4], uint32_t addr) {
    asm volatile("ldmatrix.sync.aligned.m8n8.x4.shared.b16 {%0,%1,%2,%3}, [%4];"
                 : "=r"(r[0]), "=r"(r[1]), "=r"(r[2]), "=r"(r[3]) : "r"(addr));
}
__device__ __forceinline__ void ldsm4t(uint32_t r[4], uint32_t addr) {
    asm volatile("ldmatrix.sync.aligned.m8n8.x4.trans.shared.b16 {%0,%1,%2,%3}, [%4];"
                 : "=r"(r[0]), "=r"(r[1]), "=r"(r[2]), "=r"(r[3]) : "r"(addr));
}
__device__ __forceinline__ void mma_bf16(float d[4], const uint32_t a[4],
                                         uint32_t b0, uint32_t b1) {
    asm volatile(
        "mma.sync.aligned.m16n8k16.row.col.f32.bf16.bf16.f32 "
        "{%0,%1,%2,%3}, {%4,%5,%6,%7}, {%8,%9}, {%0,%1,%2,%3};"
        : "+f"(d[0]), "+f"(d[1]), "+f"(d[2]), "+f"(d[3])
        : "r"(a[0]), "r"(a[1]), "r"(a[2]), "r"(a[3]), "r"(b0), "r"(b1));
}
__device__ __forceinline__ void split_bf16(float v, __nv_bfloat16& hi, __nv_bfloat16& lo) {
    hi = __float2bfloat16(v);
    lo = __float2bfloat16(v - __bfloat162float(hi));
}
__device__ __forceinline__ float sigmoid_fast(float x) {
    return __fdividef(1.f, 1.f + __expf(-x));
}
__device__ __forceinline__ float tanh_exp(float x) {
    // tanh(x) = 1 - 2/(e^{2x}+1); MUFU + fast div, few-ulp, stable both tails
    return 1.f - __fdividef(2.f, __expf(2.f * x) + 1.f);
}

// ---------------------------------------------------------------------------
// Big tensor GEMM: C[512][2048] = A[512,512] @ B[512,2048] via 3-pass bf16 split.
// CTA tile 64m x 128n, grid (16, 8), 256 threads (8 warps = 4m x 2n).
// Output written as bf16 hi/lo pair (Ch, Cl).
// ---------------------------------------------------------------------------
#define STAGE_BYTES 24576
#define OFF_AH 0
#define OFF_AL 4096
#define OFF_BH 8192
#define OFF_BL 16384
#define SM_TMMA (2*STAGE_BYTES)     // 49152

__global__ __launch_bounds__(256) void k_tmma(
    const __nv_bfloat16* __restrict__ Ah, const __nv_bfloat16* __restrict__ Al,
    const __nv_bfloat16* __restrict__ Bh, const __nv_bfloat16* __restrict__ Bl,
    __nv_bfloat16* __restrict__ Ch, __nv_bfloat16* __restrict__ Cl)
{
    extern __shared__ char smc[];
    const uint32_t sbase = smem_to_u32(smc);
    const int tid = threadIdx.x, wid = tid >> 5, lane = tid & 31;
    const int m0c = blockIdx.y * 64;
    const int n0c = blockIdx.x * 128;
    const int mw = (wid & 3) * 16;
    const int nw = (wid >> 2) * 64;

    float acc[8][4];
#pragma unroll
    for (int i = 0; i < 8; i++)
#pragma unroll
        for (int j = 0; j < 4; j++) acc[i][j] = 0.f;

    const int am = tid >> 2, aseg = tid & 3;
    const uint32_t aso = (uint32_t)(am * 64 + ((aseg ^ (am & 3)) << 4));

#define LOAD_STAGE(s) do {                                                         \
    const int kk = (s) * 32;                                                       \
    const uint32_t sb = sbase + ((s) & 1) * STAGE_BYTES;                           \
    cp16(sb + OFF_AH + aso, &Ah[(m0c + am) * 512 + kk + aseg * 8]);                \
    cp16(sb + OFF_AL + aso, &Al[(m0c + am) * 512 + kk + aseg * 8]);                \
    _Pragma("unroll")                                                              \
    for (int u = 0; u < 2; u++) {                                                  \
        const int unit = tid + u * 256;                                            \
        const int bk = unit >> 4, bs = unit & 15;                                  \
        const uint32_t bso = (uint32_t)(bk * 256 + ((bs ^ (bk & 7)) << 4));        \
        cp16(sb + OFF_BH + bso, &Bh[(kk + bk) * 2048 + n0c + bs * 8]);             \
        cp16(sb + OFF_BL + bso, &Bl[(kk + bk) * 2048 + n0c + bs * 8]);             \
    }                                                                              \
    cp_commit();                                                                   \
} while (0)

    LOAD_STAGE(0);
    LOAD_STAGE(1);

    for (int s = 0; s < 16; s++) {
        if (s < 14) asm volatile("cp.async.wait_group 1;" ::: "memory");
        else        asm volatile("cp.async.wait_group 0;" ::: "memory");
        __syncthreads();

        const uint32_t sb = sbase + (s & 1) * STAGE_BYTES;
#pragma unroll
        for (int kh = 0; kh < 32; kh += 16) {
            uint32_t afh[4], afl[4];
            {
                const int row = mw + (lane & 15);
                const int seg = (kh >> 3) + (lane >> 4);
                const uint32_t ad = sb + OFF_AH + row * 64 + ((seg ^ (row & 3)) << 4);
                ldsm4(afh, ad);
                ldsm4(afl, ad + (OFF_AL - OFF_AH));
            }
            uint32_t bfh[4][4], bfl[4][4];
            {
                const int bk = kh + (lane & 15);
#pragma unroll
                for (int g = 0; g < 4; g++) {
                    const int seg = (nw >> 3) + 2 * g + (lane >> 4);
                    const uint32_t bd = sb + OFF_BH + bk * 256 + ((seg ^ (bk & 7)) << 4);
                    ldsm4t(bfh[g], bd);
                    ldsm4t(bfl[g], bd + (OFF_BL - OFF_BH));
                }
            }
#pragma unroll
            for (int nf = 0; nf < 8; nf++) {
                const int g = nf >> 1, h = (nf & 1) * 2;
                mma_bf16(acc[nf], afh, bfh[g][h], bfh[g][h + 1]);
                mma_bf16(acc[nf], afh, bfl[g][h], bfl[g][h + 1]);
                mma_bf16(acc[nf], afl, bfh[g][h], bfh[g][h + 1]);
            }
        }
        __syncthreads();
        if (s + 2 < 16) LOAD_STAGE(s + 2);
    }
#undef LOAD_STAGE

    const int r0 = m0c + mw + (lane >> 2);
    const int cb = n0c + nw + (lane & 3) * 2;
#pragma unroll
    for (int nf = 0; nf < 8; nf++) {
        const int col = cb + nf * 8;
#pragma unroll
        for (int half = 0; half < 2; half++) {
            const int r = r0 + half * 8;
            const int idx = r * BH + col;
            __nv_bfloat16 h0, l0, h1, l1;
            split_bf16(acc[nf][half * 2 + 0], h0, l0);
            split_bf16(acc[nf][half * 2 + 1], h1, l1);
            __nv_bfloat162 ph; ph.x = h0; ph.y = h1;
            __nv_bfloat162 pl; pl.x = l0; pl.y = l1;
            *reinterpret_cast<__nv_bfloat162*>(&Ch[idx]) = ph;
            *reinterpret_cast<__nv_bfloat162*>(&Cl[idx]) = pl;
        }
    }
}

// ---------------------------------------------------------------------------
// Shared K=128 HMMA core for gate: A[64 rows x 128] (hi/lo) @ W[128 x 128]
// (hi/lo), 3-pass. 256 threads, 8 warps (4m x 2n). All tiles single-shot in smem.
// smem layout (dynamic): AH 0 (16KB), AL 16384, WH 32768 (32KB), WL 65536 -> 96KB
// ---------------------------------------------------------------------------
#define SM_GC 98304

template<int LDW>
__device__ __forceinline__ void hmma_k128(
    const __nv_bfloat16* __restrict__ Ah_g,  // &A[r0c*128]
    const __nv_bfloat16* __restrict__ Al_g,
    const __nv_bfloat16* __restrict__ Wh_g,  // &W[o0], row stride LDW
    const __nv_bfloat16* __restrict__ Wl_g,
    uint32_t sbase, float acc[8][4], int mw, int nw, int lane, int tid)
{
#pragma unroll
    for (int u = 0; u < 4; u++) {
        const int unit = tid + u * 256;
        const int row = unit >> 4, seg = unit & 15;
        const uint32_t so = (uint32_t)(row * 256 + ((seg ^ (row & 7)) << 4));
        cp16(sbase + 0     + so, Ah_g + row * 128 + seg * 8);
        cp16(sbase + 16384 + so, Al_g + row * 128 + seg * 8);
    }
#pragma unroll
    for (int u = 0; u < 8; u++) {
        const int unit = tid + u * 256;
        const int k = unit >> 4, seg = unit & 15;
        const uint32_t so = (uint32_t)(k * 256 + ((seg ^ (k & 7)) << 4));
        cp16(sbase + 32768 + so, Wh_g + k * LDW + seg * 8);
        cp16(sbase + 65536 + so, Wl_g + k * LDW + seg * 8);
    }
    cp_commit();
    asm volatile("cp.async.wait_group 0;" ::: "memory");
    __syncthreads();

#pragma unroll
    for (int kh = 0; kh < 8; kh++) {
        uint32_t afh[4], afl[4];
        {
            const int row = mw + (lane & 15);
            const int seg = kh * 2 + (lane >> 4);
            const uint32_t ao = (uint32_t)(row * 256 + ((seg ^ (row & 7)) << 4));
            ldsm4(afh, sbase + ao);
            ldsm4(afl, sbase + 16384 + ao);
        }
        uint32_t bfh[4][4], bfl[4][4];
        {
            const int bk = kh * 16 + (lane & 15);
#pragma unroll
            for (int g = 0; g < 4; g++) {
                const int seg = (nw >> 3) + 2 * g + (lane >> 4);
                const uint32_t wo = (uint32_t)(bk * 256 + ((seg ^ (bk & 7)) << 4));
                ldsm4t(bfh[g], sbase + 32768 + wo);
                ldsm4t(bfl[g], sbase + 65536 + wo);
            }
        }
#pragma unroll
        for (int nf = 0; nf < 8; nf++) {
            const int g = nf >> 1, h = (nf & 1) * 2;
            mma_bf16(acc[nf], afh, bfh[g][h], bfh[g][h + 1]);
            mma_bf16(acc[nf], afh, bfl[g][h], bfl[g][h + 1]);
            mma_bf16(acc[nf], afl, bfh[g][h], bfh[g][h + 1]);
        }
    }
}

// ---------------------------------------------------------------------------
// Gate (tensorized): sigmoid(AGG @ W1h + xagg*W1x + b1)
// r-half -> RH = r*h (bf16 split), u-half -> U (fp32, h-layout).
// grid (2 o-tiles, 128 r-tiles), 256 threads.   (byte-identical to round 12)
// ---------------------------------------------------------------------------
__global__ __launch_bounds__(256) void k_gate_t(
    const __nv_bfloat16* __restrict__ AGGh, const __nv_bfloat16* __restrict__ AGGl,
    const __nv_bfloat16* __restrict__ W1hh, const __nv_bfloat16* __restrict__ W1hl,
    const float* __restrict__ W1, const float* __restrict__ b1,
    const float* __restrict__ Xagg, int t,
    const __nv_bfloat16* __restrict__ Hh, const __nv_bfloat16* __restrict__ Hl,
    __nv_bfloat16* __restrict__ RHh, __nv_bfloat16* __restrict__ RHl,
    float* __restrict__ U)
{
    extern __shared__ char smc[];
    const uint32_t sbase = smem_to_u32(smc);
    const int tid = threadIdx.x, wid = tid >> 5, lane = tid & 31;
    const int mw = (wid & 3) * 16, nw = (wid >> 2) * 64;
    const int r0c = blockIdx.y * 64;
    const int o0 = blockIdx.x * 128;
    const int bit = blockIdx.x;

    float acc[8][4];
#pragma unroll
    for (int i = 0; i < 8; i++)
#pragma unroll
        for (int j = 0; j < 4; j++) acc[i][j] = 0.f;

    hmma_k128<256>(AGGh + r0c * 128, AGGl + r0c * 128, W1hh + o0, W1hl + o0,
                   sbase, acc, mw, nw, lane, tid);

    const int rr0 = r0c + mw + (lane >> 2);
#pragma unroll
    for (int half = 0; half < 2; half++) {
        const int r = rr0 + half * 8;
        const int mq = r >> 4, b = r & 15;
        const float xa = Xagg[t * (BB * NB) + b * NB + mq];
        const bool isR = (mq < 256);
        const int nbase = isR ? (2 * mq + bit) : (2 * (mq - 256) + bit);
#pragma unroll
        for (int nf = 0; nf < 8; nf++) {
            const int o = o0 + nw + (lane & 3) * 2 + nf * 8;
            const float v0 = acc[nf][half * 2 + 0] + xa * W1[o]     + b1[o];
            const float v1 = acc[nf][half * 2 + 1] + xa * W1[o + 1] + b1[o + 1];
            const float s0 = sigmoid_fast(v0);
            const float s1 = sigmoid_fast(v1);
            const int c = o & 127;
            const int idx = (nbase * 16 + b) * 128 + c;
            if (isR) {
                __nv_bfloat162 hh = *reinterpret_cast<const __nv_bfloat162*>(&Hh[idx]);
                __nv_bfloat162 hl = *reinterpret_cast<const __nv_bfloat162*>(&Hl[idx]);
                const float h0 = __bfloat162float(hh.x) + __bfloat162float(hl.x);
                const float h1 = __bfloat162float(hh.y) + __bfloat162float(hl.y);
                const float rh0 = s0 * h0, rh1 = s1 * h1;
                __nv_bfloat16 a0, c0, a1, c1;
                split_bf16(rh0, a0, c0);
                split_bf16(rh1, a1, c1);
                __nv_bfloat162 ph; ph.x = a0; ph.y = a1;
                __nv_bfloat162 pl; pl.x = c0; pl.y = c1;
                *reinterpret_cast<__nv_bfloat162*>(&RHh[idx]) = ph;
                *reinterpret_cast<__nv_bfloat162*>(&RHl[idx]) = pl;
            } else {
                *reinterpret_cast<float2*>(&U[idx]) = make_float2(s0, s1);
            }
        }
    }
}

// ---------------------------------------------------------------------------
// Candidate (tensorized, epilogue-prefetched): C = tanh(AGG2@W2h + xagg*W2x + b2);
// h_new = u*h + (1-u)*C; write Hh/Hl; fused hs1 row-reduction.
// U / Hh / Hl tiles for this CTA's rows are prefetched into smem in the same
// cp.async group as A and W, turning the epilogue's global reads into LDS.
// smem: AH 0, AL 16K, WH 32K, WL 64K, U 96K(32K), sHh 128K(16K), sHl 144K -> 160KB
// grid (1, 128), 256 threads.
// ---------------------------------------------------------------------------
#define SM_CAND 163840
#define CU_OFF  98304
#define CHH_OFF 131072
#define CHL_OFF 147456

__global__ __launch_bounds__(256) void k_cand_t(
    const __nv_bfloat16* __restrict__ AGGh, const __nv_bfloat16* __restrict__ AGGl,
    const __nv_bfloat16* __restrict__ W2hh, const __nv_bfloat16* __restrict__ W2hl,
    const float* __restrict__ W2, const float* __restrict__ b2,
    const float* __restrict__ Xagg, int t,
    const float* __restrict__ aw1, const float* __restrict__ ab1,
    const float* __restrict__ U,
    __nv_bfloat16* __restrict__ Hh, __nv_bfloat16* __restrict__ Hl,
    float* __restrict__ HS1)
{
    extern __shared__ char smc[];
    __shared__ float sRed[64];
    const uint32_t sbase = smem_to_u32(smc);
    const int tid = threadIdx.x, wid = tid >> 5, lane = tid & 31;
    const int mw = (wid & 3) * 16, nw = (wid >> 2) * 64;
    const int r0c = blockIdx.y * 64;

    // A tile (64 x 128 hi/lo, swizzled)
#pragma unroll
    for (int u = 0; u < 4; u++) {
        const int unit = tid + u * 256;
        const int row = unit >> 4, seg = unit & 15;
        const uint32_t so = (uint32_t)(row * 256 + ((seg ^ (row & 7)) << 4));
        cp16(sbase + 0     + so, AGGh + (r0c + row) * 128 + seg * 8);
        cp16(sbase + 16384 + so, AGGl + (r0c + row) * 128 + seg * 8);
    }
    // W2 (128 x 128 hi/lo, swizzled)
#pragma unroll
    for (int u = 0; u < 8; u++) {
        const int unit = tid + u * 256;
        const int k = unit >> 4, seg = unit & 15;
        const uint32_t so = (uint32_t)(k * 256 + ((seg ^ (k & 7)) << 4));
        cp16(sbase + 32768 + so, W2hh + k * 128 + seg * 8);
        cp16(sbase + 65536 + so, W2hl + k * 128 + seg * 8);
    }
    // Epilogue operand prefetch: U (64 rows x 512B), Hh/Hl (64 rows x 256B), linear
#pragma unroll
    for (int u = 0; u < 8; u++) {
        const int unit = tid + u * 256;            // 2048 16B-chunks
        const int row = unit >> 5, seg = unit & 31;
        cp16(sbase + CU_OFF + row * 512 + seg * 16, U + (r0c + row) * 128 + seg * 4);
    }
#pragma unroll
    for (int u = 0; u < 4; u++) {
        const int unit = tid + u * 256;            // 1024 16B-chunks
        const int row = unit >> 4, seg = unit & 15;
        cp16(sbase + CHH_OFF + row * 256 + seg * 16, Hh + (r0c + row) * 128 + seg * 8);
        cp16(sbase + CHL_OFF + row * 256 + seg * 16, Hl + (r0c + row) * 128 + seg * 8);
    }
    cp_commit();
    asm volatile("cp.async.wait_group 0;" ::: "memory");
    __syncthreads();

    float acc[8][4];
#pragma unroll
    for (int i = 0; i < 8; i++)
#pragma unroll
        for (int j = 0; j < 4; j++) acc[i][j] = 0.f;

#pragma unroll
    for (int kh = 0; kh < 8; kh++) {
        uint32_t afh[4], afl[4];
        {
            const int row = mw + (lane & 15);
            const int seg = kh * 2 + (lane >> 4);
            const uint32_t ao = (uint32_t)(row * 256 + ((seg ^ (row & 7)) << 4));
            ldsm4(afh, sbase + ao);
            ldsm4(afl, sbase + 16384 + ao);
        }
        uint32_t bfh[4][4], bfl[4][4];
        {
            const int bk = kh * 16 + (lane & 15);
#pragma unroll
            for (int g = 0; g < 4; g++) {
                const int seg = (nw >> 3) + 2 * g + (lane >> 4);
                const uint32_t wo = (uint32_t)(bk * 256 + ((seg ^ (bk & 7)) << 4));
                ldsm4t(bfh[g], sbase + 32768 + wo);
                ldsm4t(bfl[g], sbase + 65536 + wo);
            }
        }
#pragma unroll
        for (int nf = 0; nf < 8; nf++) {
            const int g = nf >> 1, h = (nf & 1) * 2;
            mma_bf16(acc[nf], afh, bfh[g][h], bfh[g][h + 1]);
            mma_bf16(acc[nf], afh, bfl[g][h], bfl[g][h + 1]);
            mma_bf16(acc[nf], afl, bfh[g][h], bfh[g][h + 1]);
        }
    }

    const int rr0 = r0c + mw + (lane >> 2);
    float part[2] = {0.f, 0.f};
#pragma unroll
    for (int half = 0; half < 2; half++) {
        const int r = rr0 + half * 8;
        const int lr = r - r0c;
        const int mq = r >> 4, b = r & 15;
        const float xa = Xagg[t * (BB * NB) + b * NB + mq];
#pragma unroll
        for (int nf = 0; nf < 8; nf++) {
            const int o = nw + (lane & 3) * 2 + nf * 8;
            const float pre0 = acc[nf][half * 2 + 0] + xa * W2[o]     + b2[o];
            const float pre1 = acc[nf][half * 2 + 1] + xa * W2[o + 1] + b2[o + 1];
            const float cv0 = tanh_exp(pre0);
            const float cv1 = tanh_exp(pre1);
            const float2 uu = *reinterpret_cast<const float2*>(smc + CU_OFF + lr * 512 + o * 4);
            __nv_bfloat162 hh = *reinterpret_cast<const __nv_bfloat162*>(smc + CHH_OFF + lr * 256 + o * 2);
            __nv_bfloat162 hl = *reinterpret_cast<const __nv_bfloat162*>(smc + CHL_OFF + lr * 256 + o * 2);
            const float h0 = __bfloat162float(hh.x) + __bfloat162float(hl.x);
            const float h1 = __bfloat162float(hh.y) + __bfloat162float(hl.y);
            const float hn0 = uu.x * h0 + (1.f - uu.x) * cv0;
            const float hn1 = uu.y * h1 + (1.f - uu.y) * cv1;
            const int idx = r * 128 + o;
            __nv_bfloat16 a0, c0, a1, c1;
            split_bf16(hn0, a0, c0);
            split_bf16(hn1, a1, c1);
            __nv_bfloat162 ph; ph.x = a0; ph.y = a1;
            __nv_bfloat162 pl; pl.x = c0; pl.y = c1;
            *reinterpret_cast<__nv_bfloat162*>(&Hh[idx]) = ph;
            *reinterpret_cast<__nv_bfloat162*>(&Hl[idx]) = pl;
            part[half] += hn0 * aw1[o] + hn1 * aw1[o + 1];
        }
    }
    // reduce over the 4 lanes of each quad (same row)
#pragma unroll
    for (int half = 0; half < 2; half++) {
        part[half] += __shfl_xor_sync(0xffffffffu, part[half], 1);
        part[half] += __shfl_xor_sync(0xffffffffu, part[half], 2);
    }
    if (wid >= 4 && (lane & 3) == 0) {
        sRed[mw + (lane >> 2)]     = part[0];
        sRed[mw + 8 + (lane >> 2)] = part[1];
    }
    __syncthreads();
    if (wid < 4 && (lane & 3) == 0) {
        const float abv = ab1[0];
#pragma unroll
        for (int half = 0; half < 2; half++) {
            const int lr = mw + half * 8 + (lane >> 2);
            const int r = r0c + lr;
            const int mq = r >> 4, b = r & 15;
            HS1[b * (TT * NB) + t * NB + mq] = part[half] + sRed[lr] + abv;
        }
    }
}

// ---------------------------------------------------------------------------
// One-time splits
// ---------------------------------------------------------------------------
__global__ void k_splitL(const float* __restrict__ L,
                         __nv_bfloat16* __restrict__ Lh, __nv_bfloat16* __restrict__ Ll)
{
    int i = blockIdx.x * 512 + threadIdx.x;
    __nv_bfloat16 hi, lo;
    split_bf16(L[i], hi, lo);
    Lh[i] = hi; Ll[i] = lo;
}

__global__ void k_splitW(const float* __restrict__ W1, const float* __restrict__ W2,
                         __nv_bfloat16* __restrict__ W1h, __nv_bfloat16* __restrict__ W1l,
                         __nv_bfloat16* __restrict__ W2h, __nv_bfloat16* __restrict__ W2l)
{
    int i = blockIdx.x * 256 + threadIdx.x;
    __nv_bfloat16 hi, lo;
    if (i < 128 * 256) {
        split_bf16(W1[256 + i], hi, lo);   // skip row 0 (x weight)
        W1h[i] = hi; W1l[i] = lo;
    } else {
        int j = i - 128 * 256;
        split_bf16(W2[128 + j], hi, lo);   // skip row 0
        W2h[j] = hi; W2l[j] = lo;
    }
}

// ---------------------------------------------------------------------------
// XAGG precompute (runs once; not hot)
// ---------------------------------------------------------------------------
__global__ __launch_bounds__(256) void k_xagg(
    const float* __restrict__ X, const float* __restrict__ L, float* __restrict__ XAGG)
{
    __shared__ float As[16][64];
    __shared__ float Bs[16][64];
    const int tid = threadIdx.x;
    const int tx = tid & 15, ty = tid >> 4;
    const int r0 = blockIdx.y * 64;
    const int m0 = blockIdx.x * 64;

    float acc[4][4];
#pragma unroll
    for (int i = 0; i < 4; i++)
#pragma unroll
        for (int j = 0; j < 4; j++) acc[i][j] = 0.f;

    const int row = tid >> 2;
    const int kq  = (tid & 3) * 4;

    for (int k0 = 0; k0 < 512; k0 += 16) {
        float4 av = *reinterpret_cast<const float4*>(&X[(r0 + row) * 512 + k0 + kq]);
        As[kq + 0][row] = av.x; As[kq + 1][row] = av.y;
        As[kq + 2][row] = av.z; As[kq + 3][row] = av.w;
        float4 bv = *reinterpret_cast<const float4*>(&L[(m0 + row) * 512 + k0 + kq]);
        Bs[kq + 0][row] = bv.x; Bs[kq + 1][row] = bv.y;
        Bs[kq + 2][row] = bv.z; Bs[kq + 3][row] = bv.w;
        __syncthreads();
#pragma unroll
        for (int k = 0; k < 16; k++) {
            float4 a4 = *reinterpret_cast<const float4*>(&As[k][ty * 4]);
            float4 b4 = *reinterpret_cast<const float4*>(&Bs[k][tx * 4]);
            float a_[4] = {a4.x, a4.y, a4.z, a4.w};
            float b_[4] = {b4.x, b4.y, b4.z, b4.w};
#pragma unroll
            for (int i = 0; i < 4; i++)
#pragma unroll
                for (int j = 0; j < 4; j++)
                    acc[i][j] += a_[i] * b_[j];
        }
        __syncthreads();
    }
#pragma unroll
    for (int i = 0; i < 4; i++) {
        int bt = r0 + ty * 4 + i;
        int b = bt >> 6, tt = bt & 63;
#pragma unroll
        for (int j = 0; j < 4; j++)
            XAGG[tt * (BB * NB) + b * NB + m0 + tx * 4 + j] = acc[i][j];
    }
}

// ---------------------------------------------------------------------------
// Attention f,g + softmax beta per batch. grid 16, 256 thr.
// ---------------------------------------------------------------------------
__global__ void k_fg(const float* __restrict__ HS1,
                     const float* __restrict__ w2, const float* __restrict__ w3,
                     const float* __restrict__ b2p, const float* __restrict__ b3p,
                     float* __restrict__ BETA)
{
    __shared__ float sf[64], sg[64], st[64];
    const int b = blockIdx.x, tid = threadIdx.x;
    const int w = tid >> 5, lane = tid & 31;
    for (int t = w; t < 64; t += 8) {
        float fs = 0.f, gs = 0.f;
        for (int n = lane; n < 512; n += 32) {
            float v = HS1[b * (TT * NB) + t * NB + n];
            fs += v * w2[n];
            gs += v * w3[n];
        }
#pragma unroll
        for (int off = 16; off; off >>= 1) {
            fs += __shfl_down_sync(0xffffffffu, fs, off);
            gs += __shfl_down_sync(0xffffffffu, gs, off);
        }
        if (lane == 0) { sf[t] = fs + b2p[0]; sg[t] = gs + b3p[0]; }
    }
    __syncthreads();
    if (tid == 0) {
        float mx = -1e30f;
        for (int t = 0; t < 64; t++) { st[t] = sf[t] * sg[t]; mx = fmaxf(mx, st[t]); }
        float sum = 0.f;
        for (int t = 0; t < 64; t++) { st[t] = expf(st[t] - mx); sum += st[t]; }
        float inv = 1.f / sum;
        for (int t = 0; t < 64; t++) BETA[b * 64 + t] = st[t] * inv;
    }
}

// ---------------------------------------------------------------------------
// Output: out[b,p,n] = sum_t beta[b,t]*hs1[b,t,n]*W_out[t,p] + b_out[p]
// ---------------------------------------------------------------------------
__global__ void k_out(const float* __restrict__ HS1, const float* __restrict__ BETA,
                      const float* __restrict__ Wout, const float* __restrict__ bout,
                      float* __restrict__ out)
{
    const int idx = blockIdx.x * 256 + threadIdx.x;
    const int b = idx >> 9, n = idx & 511;
    float acc[PP];
#pragma unroll
    for (int p = 0; p < PP; p++) acc[p] = 0.f;
    for (int t = 0; t < 64; t++) {
        float v = BETA[b * 64 + t] * HS1[b * (TT * NB) + t * NB + n];
#pragma unroll
        for (int p = 0; p < PP; p++) acc[p] += v * Wout[t * PP + p];
    }
#pragma unroll
    for (int p = 0; p < PP; p++)
        out[b * (PP * NB) + p * NB + n] = acc[p] + bout[p];
}

// ---------------------------------------------------------------------------
extern "C" void kernel_launch(void* const* d_in, const int* in_sizes, int n_in,
                              void* d_out, int out_size)
{
    (void)in_sizes; (void)n_in; (void)out_size;
    const float* X    = (const float*)d_in[0];
    const float* L    = (const float*)d_in[1];
    const float* W1   = (const float*)d_in[2];
    const float* b1   = (const float*)d_in[3];
    const float* W2   = (const float*)d_in[4];
    const float* b2   = (const float*)d_in[5];
    const float* aw1  = (const float*)d_in[6];
    const float* aw2  = (const float*)d_in[7];
    const float* aw3  = (const float*)d_in[8];
    const float* ab1  = (const float*)d_in[9];
    const float* ab2  = (const float*)d_in[10];
    const float* ab3  = (const float*)d_in[11];
    const float* Wout = (const float*)d_in[12];
    const float* bout = (const float*)d_in[13];
    float* out = (float*)d_out;

    float *U, *XA, *HS1, *BETA;
    __nv_bfloat16 *Lh, *Ll, *Hh, *Hl, *RHh, *RHl, *AGGh, *AGGl;
    __nv_bfloat16 *W1hh, *W1hl, *W2hh, *W2hl;
    cudaGetSymbolAddress((void**)&U,    g_U);
    cudaGetSymbolAddress((void**)&XA,   g_XAGG);
    cudaGetSymbolAddress((void**)&HS1,  g_HS1);
    cudaGetSymbolAddress((void**)&BETA, g_BETA);
    cudaGetSymbolAddress((void**)&Lh,   g_Lh);
    cudaGetSymbolAddress((void**)&Ll,   g_Ll);
    cudaGetSymbolAddress((void**)&Hh,   g_Hh);
    cudaGetSymbolAddress((void**)&Hl,   g_Hl);
    cudaGetSymbolAddress((void**)&RHh,  g_RHh);
    cudaGetSymbolAddress((void**)&RHl,  g_RHl);
    cudaGetSymbolAddress((void**)&AGGh, g_AGGh);
    cudaGetSymbolAddress((void**)&AGGl, g_AGGl);
    cudaGetSymbolAddress((void**)&W1hh, g_W1hh);
    cudaGetSymbolAddress((void**)&W1hl, g_W1hl);
    cudaGetSymbolAddress((void**)&W2hh, g_W2hh);
    cudaGetSymbolAddress((void**)&W2hl, g_W2hl);

    cudaFuncSetAttribute(k_tmma,   cudaFuncAttributeMaxDynamicSharedMemorySize, SM_TMMA);
    cudaFuncSetAttribute(k_gate_t, cudaFuncAttributeMaxDynamicSharedMemorySize, SM_GC);
    cudaFuncSetAttribute(k_cand_t, cudaFuncAttributeMaxDynamicSharedMemorySize, SM_CAND);

    cudaMemsetAsync(Hh,   0, sizeof(__nv_bfloat16) * RWS * HH);
    cudaMemsetAsync(Hl,   0, sizeof(__nv_bfloat16) * RWS * HH);
    cudaMemsetAsync(AGGh, 0, sizeof(__nv_bfloat16) * RWS * HH);
    cudaMemsetAsync(AGGl, 0, sizeof(__nv_bfloat16) * RWS * HH);

    k_splitL<<<512, 512>>>(L, Lh, Ll);
    k_splitW<<<192, 256>>>(W1, W2, W1hh, W1hl, W2hh, W2hl);
    k_xagg<<<dim3(8, 16), 256>>>(X, L, XA);

    for (int t = 0; t < TT; t++) {
        if (t) k_tmma<<<dim3(16, 8), 256, SM_TMMA>>>(Lh, Ll, Hh, Hl, AGGh, AGGl);
        k_gate_t<<<dim3(2, 128), 256, SM_GC>>>(AGGh, AGGl, W1hh, W1hl, W1, b1,
                                               XA, t, Hh, Hl, RHh, RHl, U);
        if (t) k_tmma<<<dim3(16, 8), 256, SM_TMMA>>>(Lh, Ll, RHh, RHl, AGGh, AGGl);
        k_cand_t<<<dim3(1, 128), 256, SM_CAND>>>(AGGh, AGGl, W2hh, W2hl, W2, b2,
                                                 XA, t, aw1, ab1, U, Hh, Hl, HS1);
    }

    k_fg<<<16, 256>>>(HS1, aw2, aw3, ab2, ab3, BETA);
    k_out<<<32, 256>>>(HS1, BETA, Wout, bout, out);
}

// round 15
// speedup vs baseline: 1.1972x; 1.0164x over previous
#include <cuda_runtime.h>
#include <cuda_bf16.h>
#include <cstdint>

// Problem constants: B=16, T=64, N=512, H=128, P=12
#define NB   512
#define BB   16
#define TT   64
#define HH   128
#define PP   12
#define RWS  (NB*BB)          // 8192 rows (n,b)
#define BH   (BB*HH)          // 2048

// Scratch (device globals; no allocation allowed)
__device__ float g_U   [RWS*HH];          // update gate, h-layout
__device__ float g_XAGG[TT*BB*NB];        // [t][b][m] = (L @ x_t)[b,m]
__device__ float g_HS1 [BB*TT*NB];        // [b][t][n]
__device__ float g_BETA[BB*TT];
__device__ __nv_bfloat16 g_Lh  [NB*NB];   // L hi/lo (A of big GEMM)
__device__ __nv_bfloat16 g_Ll  [NB*NB];
__device__ __nv_bfloat16 g_Hh  [RWS*HH];  // H hi/lo
__device__ __nv_bfloat16 g_Hl  [RWS*HH];
__device__ __nv_bfloat16 g_RHh [RWS*HH];  // (r*h) hi/lo
__device__ __nv_bfloat16 g_RHl [RWS*HH];
__device__ __nv_bfloat16 g_AGGh[RWS*HH];  // L@B result hi/lo
__device__ __nv_bfloat16 g_AGGl[RWS*HH];
__device__ __nv_bfloat16 g_W1hh[HH*2*HH]; // W1 rows 1..128 hi/lo [128][256]
__device__ __nv_bfloat16 g_W1hl[HH*2*HH];
__device__ __nv_bfloat16 g_W2hh[HH*HH];   // W2 rows 1..128 hi/lo [128][128]
__device__ __nv_bfloat16 g_W2hl[HH*HH];

// ---------------------------------------------------------------------------
// Helpers
// ---------------------------------------------------------------------------
__device__ __forceinline__ uint32_t smem_to_u32(const void* p) {
    uint32_t a;
    asm("{ .reg .u64 t; cvta.to.shared.u64 t, %1; cvt.u32.u64 %0, t; }" : "=r"(a) : "l"(p));
    return a;
}
__device__ __forceinline__ void cp16(uint32_t saddr, const void* gaddr) {
    asm volatile("cp.async.cg.shared.global [%0], [%1], 16;" :: "r"(saddr), "l"(gaddr));
}
__device__ __forceinline__ void cp_commit() {
    asm volatile("cp.async.commit_group;" ::: "memory");
}
__device__ __forceinline__ void ldsm4(uint32_t r[4], uint32_t addr) {
    asm volatile("ldmatrix.sync.aligned.m8n8.x4.shared.b16 {%0,%1,%2,%3}, [%4];"
                 : "=r"(r[0]), "=r"(r[1]), "=r"(r[2]), "=r"(r[3]) : "r"(addr));
}
__device__ __forceinline__ void ldsm4t(uint32_t r[4], uint32_t addr) {
    asm volatile("ldmatrix.sync.aligned.m8n8.x4.trans.shared.b16 {%0,%1,%2,%3}, [%4];"
                 : "=r"(r[0]), "=r"(r[1]), "=r"(r[2]), "=r"(r[3]) : "r"(addr));
}
__device__ __forceinline__ void mma_bf16(float d[4], const uint32_t a[4],
                                         uint32_t b0, uint32_t b1) {
    asm volatile(
        "mma.sync.aligned.m16n8k16.row.col.f32.bf16.bf16.f32 "
        "{%0,%1,%2,%3}, {%4,%5,%6,%7}, {%8,%9}, {%0,%1,%2,%3};"
        : "+f"(d[0]), "+f"(d[1]), "+f"(d[2]), "+f"(d[3])
        : "r"(a[0]), "r"(a[1]), "r"(a[2]), "r"(a[3]), "r"(b0), "r"(b1));
}
__device__ __forceinline__ void split_bf16(float v, __nv_bfloat16& hi, __nv_bfloat16& lo) {
    hi = __float2bfloat16(v);
    lo = __float2bfloat16(v - __bfloat162float(hi));
}
__device__ __forceinline__ float sigmoid_fast(float x) {
    return __fdividef(1.f, 1.f + __expf(-x));
}
__device__ __forceinline__ float tanh_exp(float x) {
    // tanh(x) = 1 - 2/(e^{2x}+1); MUFU + fast div, few-ulp, stable both tails
    return 1.f - __fdividef(2.f, __expf(2.f * x) + 1.f);
}

// ---------------------------------------------------------------------------
// Big tensor GEMM: C[512][2048] = A[512,512] @ B[512,2048] via 3-pass bf16 split.
// CTA tile 64m x 64n, grid (32, 8) = 256 CTAs, 256 threads (8 warps = 4m x 2n).
// 32KB smem -> 2 CTAs resident per SM: sync/wait bubbles overlap across CTAs.
// Output written as bf16 hi/lo pair (Ch, Cl).
// ---------------------------------------------------------------------------
#define STAGE_BYTES 16384
#define OFF_AH 0
#define OFF_AL 4096
#define OFF_BH 8192
#define OFF_BL 12288
#define SM_TMMA (2*STAGE_BYTES)     // 32768

__global__ __launch_bounds__(256) void k_tmma(
    const __nv_bfloat16* __restrict__ Ah, const __nv_bfloat16* __restrict__ Al,
    const __nv_bfloat16* __restrict__ Bh, const __nv_bfloat16* __restrict__ Bl,
    __nv_bfloat16* __restrict__ Ch, __nv_bfloat16* __restrict__ Cl)
{
    extern __shared__ char smc[];
    const uint32_t sbase = smem_to_u32(smc);
    const int tid = threadIdx.x, wid = tid >> 5, lane = tid & 31;
    const int m0c = blockIdx.y * 64;
    const int n0c = blockIdx.x * 64;
    const int mw = (wid & 3) * 16;
    const int nw = (wid >> 2) * 32;

    float acc[4][4];
#pragma unroll
    for (int i = 0; i < 4; i++)
#pragma unroll
        for (int j = 0; j < 4; j++) acc[i][j] = 0.f;

    // A: 64 rows x 4 segs (16B); B: 32 k-rows x 8 segs (row = 64 bf16 = 128B)
    const int am = tid >> 2, aseg = tid & 3;
    const uint32_t aso = (uint32_t)(am * 64 + ((aseg ^ (am & 3)) << 4));
    const int bk0 = tid >> 3, bseg = tid & 7;
    const uint32_t bso = (uint32_t)(bk0 * 128 + ((bseg ^ (bk0 & 7)) << 4));

#define LOAD_STAGE(s) do {                                                         \
    const int kk = (s) * 32;                                                       \
    const uint32_t sb = sbase + ((s) & 1) * STAGE_BYTES;                           \
    cp16(sb + OFF_AH + aso, &Ah[(m0c + am) * 512 + kk + aseg * 8]);                \
    cp16(sb + OFF_AL + aso, &Al[(m0c + am) * 512 + kk + aseg * 8]);                \
    cp16(sb + OFF_BH + bso, &Bh[(kk + bk0) * 2048 + n0c + bseg * 8]);              \
    cp16(sb + OFF_BL + bso, &Bl[(kk + bk0) * 2048 + n0c + bseg * 8]);              \
    cp_commit();                                                                   \
} while (0)

    LOAD_STAGE(0);
    LOAD_STAGE(1);

    for (int s = 0; s < 16; s++) {
        if (s < 14) asm volatile("cp.async.wait_group 1;" ::: "memory");
        else        asm volatile("cp.async.wait_group 0;" ::: "memory");
        __syncthreads();

        const uint32_t sb = sbase + (s & 1) * STAGE_BYTES;
#pragma unroll
        for (int kh = 0; kh < 32; kh += 16) {
            uint32_t afh[4], afl[4];
            {
                const int row = mw + (lane & 15);
                const int seg = (kh >> 3) + (lane >> 4);
                const uint32_t ad = sb + OFF_AH + row * 64 + ((seg ^ (row & 3)) << 4);
                ldsm4(afh, ad);
                ldsm4(afl, ad + (OFF_AL - OFF_AH));
            }
            uint32_t bfh[2][4], bfl[2][4];
            {
                const int bk = kh + (lane & 15);
#pragma unroll
                for (int g = 0; g < 2; g++) {
                    const int seg = (nw >> 3) + 2 * g + (lane >> 4);
                    const uint32_t bd = sb + OFF_BH + bk * 128 + ((seg ^ (bk & 7)) << 4);
                    ldsm4t(bfh[g], bd);
                    ldsm4t(bfl[g], bd + (OFF_BL - OFF_BH));
                }
            }
#pragma unroll
            for (int nf = 0; nf < 4; nf++) {
                const int g = nf >> 1, h = (nf & 1) * 2;
                mma_bf16(acc[nf], afh, bfh[g][h], bfh[g][h + 1]);
                mma_bf16(acc[nf], afh, bfl[g][h], bfl[g][h + 1]);
                mma_bf16(acc[nf], afl, bfh[g][h], bfh[g][h + 1]);
            }
        }
        __syncthreads();
        if (s + 2 < 16) LOAD_STAGE(s + 2);
    }
#undef LOAD_STAGE

    const int r0 = m0c + mw + (lane >> 2);
    const int cb = n0c + nw + (lane & 3) * 2;
#pragma unroll
    for (int nf = 0; nf < 4; nf++) {
        const int col = cb + nf * 8;
#pragma unroll
        for (int half = 0; half < 2; half++) {
            const int r = r0 + half * 8;
            const int idx = r * BH + col;
            __nv_bfloat16 h0, l0, h1, l1;
            split_bf16(acc[nf][half * 2 + 0], h0, l0);
            split_bf16(acc[nf][half * 2 + 1], h1, l1);
            __nv_bfloat162 ph; ph.x = h0; ph.y = h1;
            __nv_bfloat162 pl; pl.x = l0; pl.y = l1;
            *reinterpret_cast<__nv_bfloat162*>(&Ch[idx]) = ph;
            *reinterpret_cast<__nv_bfloat162*>(&Cl[idx]) = pl;
        }
    }
}

// ---------------------------------------------------------------------------
// Shared K=128 HMMA core for gate: A[64 rows x 128] (hi/lo) @ W[128 x 128]
// (hi/lo), 3-pass. 256 threads, 8 warps (4m x 2n). All tiles single-shot in smem.
// smem layout (dynamic): AH 0 (16KB), AL 16384, WH 32768 (32KB), WL 65536 -> 96KB
// ---------------------------------------------------------------------------
#define SM_GC 98304

template<int LDW>
__device__ __forceinline__ void hmma_k128(
    const __nv_bfloat16* __restrict__ Ah_g,  // &A[r0c*128]
    const __nv_bfloat16* __restrict__ Al_g,
    const __nv_bfloat16* __restrict__ Wh_g,  // &W[o0], row stride LDW
    const __nv_bfloat16* __restrict__ Wl_g,
    uint32_t sbase, float acc[8][4], int mw, int nw, int lane, int tid)
{
#pragma unroll
    for (int u = 0; u < 4; u++) {
        const int unit = tid + u * 256;
        const int row = unit >> 4, seg = unit & 15;
        const uint32_t so = (uint32_t)(row * 256 + ((seg ^ (row & 7)) << 4));
        cp16(sbase + 0     + so, Ah_g + row * 128 + seg * 8);
        cp16(sbase + 16384 + so, Al_g + row * 128 + seg * 8);
    }
#pragma unroll
    for (int u = 0; u < 8; u++) {
        const int unit = tid + u * 256;
        const int k = unit >> 4, seg = unit & 15;
        const uint32_t so = (uint32_t)(k * 256 + ((seg ^ (k & 7)) << 4));
        cp16(sbase + 32768 + so, Wh_g + k * LDW + seg * 8);
        cp16(sbase + 65536 + so, Wl_g + k * LDW + seg * 8);
    }
    cp_commit();
    asm volatile("cp.async.wait_group 0;" ::: "memory");
    __syncthreads();

#pragma unroll
    for (int kh = 0; kh < 8; kh++) {
        uint32_t afh[4], afl[4];
        {
            const int row = mw + (lane & 15);
            const int seg = kh * 2 + (lane >> 4);
            const uint32_t ao = (uint32_t)(row * 256 + ((seg ^ (row & 7)) << 4));
            ldsm4(afh, sbase + ao);
            ldsm4(afl, sbase + 16384 + ao);
        }
        uint32_t bfh[4][4], bfl[4][4];
        {
            const int bk = kh * 16 + (lane & 15);
#pragma unroll
            for (int g = 0; g < 4; g++) {
                const int seg = (nw >> 3) + 2 * g + (lane >> 4);
                const uint32_t wo = (uint32_t)(bk * 256 + ((seg ^ (bk & 7)) << 4));
                ldsm4t(bfh[g], sbase + 32768 + wo);
                ldsm4t(bfl[g], sbase + 65536 + wo);
            }
        }
#pragma unroll
        for (int nf = 0; nf < 8; nf++) {
            const int g = nf >> 1, h = (nf & 1) * 2;
            mma_bf16(acc[nf], afh, bfh[g][h], bfh[g][h + 1]);
            mma_bf16(acc[nf], afh, bfl[g][h], bfl[g][h + 1]);
            mma_bf16(acc[nf], afl, bfh[g][h], bfh[g][h + 1]);
        }
    }
}

// ---------------------------------------------------------------------------
// Gate (tensorized): sigmoid(AGG @ W1h + xagg*W1x + b1)
// r-half -> RH = r*h (bf16 split), u-half -> U (fp32, h-layout).
// grid (2 o-tiles, 128 r-tiles), 256 threads.
// ---------------------------------------------------------------------------
__global__ __launch_bounds__(256) void k_gate_t(
    const __nv_bfloat16* __restrict__ AGGh, const __nv_bfloat16* __restrict__ AGGl,
    const __nv_bfloat16* __restrict__ W1hh, const __nv_bfloat16* __restrict__ W1hl,
    const float* __restrict__ W1, const float* __restrict__ b1,
    const float* __restrict__ Xagg, int t,
    const __nv_bfloat16* __restrict__ Hh, const __nv_bfloat16* __restrict__ Hl,
    __nv_bfloat16* __restrict__ RHh, __nv_bfloat16* __restrict__ RHl,
    float* __restrict__ U)
{
    extern __shared__ char smc[];
    const uint32_t sbase = smem_to_u32(smc);
    const int tid = threadIdx.x, wid = tid >> 5, lane = tid & 31;
    const int mw = (wid & 3) * 16, nw = (wid >> 2) * 64;
    const int r0c = blockIdx.y * 64;
    const int o0 = blockIdx.x * 128;
    const int bit = blockIdx.x;

    float acc[8][4];
#pragma unroll
    for (int i = 0; i < 8; i++)
#pragma unroll
        for (int j = 0; j < 4; j++) acc[i][j] = 0.f;

    hmma_k128<256>(AGGh + r0c * 128, AGGl + r0c * 128, W1hh + o0, W1hl + o0,
                   sbase, acc, mw, nw, lane, tid);

    const int rr0 = r0c + mw + (lane >> 2);
#pragma unroll
    for (int half = 0; half < 2; half++) {
        const int r = rr0 + half * 8;
        const int mq = r >> 4, b = r & 15;
        const float xa = Xagg[t * (BB * NB) + b * NB + mq];
        const bool isR = (mq < 256);
        const int nbase = isR ? (2 * mq + bit) : (2 * (mq - 256) + bit);
#pragma unroll
        for (int nf = 0; nf < 8; nf++) {
            const int o = o0 + nw + (lane & 3) * 2 + nf * 8;
            const float v0 = acc[nf][half * 2 + 0] + xa * W1[o]     + b1[o];
            const float v1 = acc[nf][half * 2 + 1] + xa * W1[o + 1] + b1[o + 1];
            const float s0 = sigmoid_fast(v0);
            const float s1 = sigmoid_fast(v1);
            const int c = o & 127;
            const int idx = (nbase * 16 + b) * 128 + c;
            if (isR) {
                __nv_bfloat162 hh = *reinterpret_cast<const __nv_bfloat162*>(&Hh[idx]);
                __nv_bfloat162 hl = *reinterpret_cast<const __nv_bfloat162*>(&Hl[idx]);
                const float h0 = __bfloat162float(hh.x) + __bfloat162float(hl.x);
                const float h1 = __bfloat162float(hh.y) + __bfloat162float(hl.y);
                const float rh0 = s0 * h0, rh1 = s1 * h1;
                __nv_bfloat16 a0, c0, a1, c1;
                split_bf16(rh0, a0, c0);
                split_bf16(rh1, a1, c1);
                __nv_bfloat162 ph; ph.x = a0; ph.y = a1;
                __nv_bfloat162 pl; pl.x = c0; pl.y = c1;
                *reinterpret_cast<__nv_bfloat162*>(&RHh[idx]) = ph;
                *reinterpret_cast<__nv_bfloat162*>(&RHl[idx]) = pl;
            } else {
                *reinterpret_cast<float2*>(&U[idx]) = make_float2(s0, s1);
            }
        }
    }
}

// ---------------------------------------------------------------------------
// Candidate (tensorized, epilogue-prefetched): C = tanh(AGG2@W2h + xagg*W2x + b2);
// h_new = u*h + (1-u)*C; write Hh/Hl; fused hs1 row-reduction.
// U / Hh / Hl tiles prefetched into smem with A and W (epilogue reads = LDS).
// smem: AH 0, AL 16K, WH 32K, WL 64K, U 96K(32K), sHh 128K(16K), sHl 144K -> 160KB
// grid (1, 128), 256 threads.
// ---------------------------------------------------------------------------
#define SM_CAND 163840
#define CU_OFF  98304
#define CHH_OFF 131072
#define CHL_OFF 147456

__global__ __launch_bounds__(256) void k_cand_t(
    const __nv_bfloat16* __restrict__ AGGh, const __nv_bfloat16* __restrict__ AGGl,
    const __nv_bfloat16* __restrict__ W2hh, const __nv_bfloat16* __restrict__ W2hl,
    const float* __restrict__ W2, const float* __restrict__ b2,
    const float* __restrict__ Xagg, int t,
    const float* __restrict__ aw1, const float* __restrict__ ab1,
    const float* __restrict__ U,
    __nv_bfloat16* __restrict__ Hh, __nv_bfloat16* __restrict__ Hl,
    float* __restrict__ HS1)
{
    extern __shared__ char smc[];
    __shared__ float sRed[64];
    const uint32_t sbase = smem_to_u32(smc);
    const int tid = threadIdx.x, wid = tid >> 5, lane = tid & 31;
    const int mw = (wid & 3) * 16, nw = (wid >> 2) * 64;
    const int r0c = blockIdx.y * 64;

    // A tile (64 x 128 hi/lo, swizzled)
#pragma unroll
    for (int u = 0; u < 4; u++) {
        const int unit = tid + u * 256;
        const int row = unit >> 4, seg = unit & 15;
        const uint32_t so = (uint32_t)(row * 256 + ((seg ^ (row & 7)) << 4));
        cp16(sbase + 0     + so, AGGh + (r0c + row) * 128 + seg * 8);
        cp16(sbase + 16384 + so, AGGl + (r0c + row) * 128 + seg * 8);
    }
    // W2 (128 x 128 hi/lo, swizzled)
#pragma unroll
    for (int u = 0; u < 8; u++) {
        const int unit = tid + u * 256;
        const int k = unit >> 4, seg = unit & 15;
        const uint32_t so = (uint32_t)(k * 256 + ((seg ^ (k & 7)) << 4));
        cp16(sbase + 32768 + so, W2hh + k * 128 + seg * 8);
        cp16(sbase + 65536 + so, W2hl + k * 128 + seg * 8);
    }
    // Epilogue operand prefetch: U (64 rows x 512B), Hh/Hl (64 rows x 256B), linear
#pragma unroll
    for (int u = 0; u < 8; u++) {
        const int unit = tid + u * 256;            // 2048 16B-chunks
        const int row = unit >> 5, seg = unit & 31;
        cp16(sbase + CU_OFF + row * 512 + seg * 16, U + (r0c + row) * 128 + seg * 4);
    }
#pragma unroll
    for (int u = 0; u < 4; u++) {
        const int unit = tid + u * 256;            // 1024 16B-chunks
        const int row = unit >> 4, seg = unit & 15;
        cp16(sbase + CHH_OFF + row * 256 + seg * 16, Hh + (r0c + row) * 128 + seg * 8);
        cp16(sbase + CHL_OFF + row * 256 + seg * 16, Hl + (r0c + row) * 128 + seg * 8);
    }
    cp_commit();
    asm volatile("cp.async.wait_group 0;" ::: "memory");
    __syncthreads();

    float acc[8][4];
#pragma unroll
    for (int i = 0; i < 8; i++)
#pragma unroll
        for (int j = 0; j < 4; j++) acc[i][j] = 0.f;

#pragma unroll
    for (int kh = 0; kh < 8; kh++) {
        uint32_t afh[4], afl[4];
        {
            const int row = mw + (lane & 15);
            const int seg = kh * 2 + (lane >> 4);
            const uint32_t ao = (uint32_t)(row * 256 + ((seg ^ (row & 7)) << 4));
            ldsm4(afh, sbase + ao);
            ldsm4(afl, sbase + 16384 + ao);
        }
        uint32_t bfh[4][4], bfl[4][4];
        {
            const int bk = kh * 16 + (lane & 15);
#pragma unroll
            for (int g = 0; g < 4; g++) {
                const int seg = (nw >> 3) + 2 * g + (lane >> 4);
                const uint32_t wo = (uint32_t)(bk * 256 + ((seg ^ (bk & 7)) << 4));
                ldsm4t(bfh[g], sbase + 32768 + wo);
                ldsm4t(bfl[g], sbase + 65536 + wo);
            }
        }
#pragma unroll
        for (int nf = 0; nf < 8; nf++) {
            const int g = nf >> 1, h = (nf & 1) * 2;
            mma_bf16(acc[nf], afh, bfh[g][h], bfh[g][h + 1]);
            mma_bf16(acc[nf], afh, bfl[g][h], bfl[g][h + 1]);
            mma_bf16(acc[nf], afl, bfh[g][h], bfh[g][h + 1]);
        }
    }

    const int rr0 = r0c + mw + (lane >> 2);
    float part[2] = {0.f, 0.f};
#pragma unroll
    for (int half = 0; half < 2; half++) {
        const int r = rr0 + half * 8;
        const int lr = r - r0c;
        const int mq = r >> 4, b = r & 15;
        const float xa = Xagg[t * (BB * NB) + b * NB + mq];
#pragma unroll
        for (int nf = 0; nf < 8; nf++) {
            const int o = nw + (lane & 3) * 2 + nf * 8;
            const float pre0 = acc[nf][half * 2 + 0] + xa * W2[o]     + b2[o];
            const float pre1 = acc[nf][half * 2 + 1] + xa * W2[o + 1] + b2[o + 1];
            const float cv0 = tanh_exp(pre0);
            const float cv1 = tanh_exp(pre1);
            const float2 uu = *reinterpret_cast<const float2*>(smc + CU_OFF + lr * 512 + o * 4);
            __nv_bfloat162 hh = *reinterpret_cast<const __nv_bfloat162*>(smc + CHH_OFF + lr * 256 + o * 2);
            __nv_bfloat162 hl = *reinterpret_cast<const __nv_bfloat162*>(smc + CHL_OFF + lr * 256 + o * 2);
            const float h0 = __bfloat162float(hh.x) + __bfloat162float(hl.x);
            const float h1 = __bfloat162float(hh.y) + __bfloat162float(hl.y);
            const float hn0 = uu.x * h0 + (1.f - uu.x) * cv0;
            const float hn1 = uu.y * h1 + (1.f - uu.y) * cv1;
            const int idx = r * 128 + o;
            __nv_bfloat16 a0, c0, a1, c1;
            split_bf16(hn0, a0, c0);
            split_bf16(hn1, a1, c1);
            __nv_bfloat162 ph; ph.x = a0; ph.y = a1;
            __nv_bfloat162 pl; pl.x = c0; pl.y = c1;
            *reinterpret_cast<__nv_bfloat162*>(&Hh[idx]) = ph;
            *reinterpret_cast<__nv_bfloat162*>(&Hl[idx]) = pl;
            part[half] += hn0 * aw1[o] + hn1 * aw1[o + 1];
        }
    }
    // reduce over the 4 lanes of each quad (same row)
#pragma unroll
    for (int half = 0; half < 2; half++) {
        part[half] += __shfl_xor_sync(0xffffffffu, part[half], 1);
        part[half] += __shfl_xor_sync(0xffffffffu, part[half], 2);
    }
    if (wid >= 4 && (lane & 3) == 0) {
        sRed[mw + (lane >> 2)]     = part[0];
        sRed[mw + 8 + (lane >> 2)] = part[1];
    }
    __syncthreads();
    if (wid < 4 && (lane & 3) == 0) {
        const float abv = ab1[0];
#pragma unroll
        for (int half = 0; half < 2; half++) {
            const int lr = mw + half * 8 + (lane >> 2);
            const int r = r0c + lr;
            const int mq = r >> 4, b = r & 15;
            HS1[b * (TT * NB) + t * NB + mq] = part[half] + sRed[lr] + abv;
        }
    }
}

// ---------------------------------------------------------------------------
// One-time splits
// ---------------------------------------------------------------------------
__global__ void k_splitL(const float* __restrict__ L,
                         __nv_bfloat16* __restrict__ Lh, __nv_bfloat16* __restrict__ Ll)
{
    int i = blockIdx.x * 512 + threadIdx.x;
    __nv_bfloat16 hi, lo;
    split_bf16(L[i], hi, lo);
    Lh[i] = hi; Ll[i] = lo;
}

__global__ void k_splitW(const float* __restrict__ W1, const float* __restrict__ W2,
                         __nv_bfloat16* __restrict__ W1h, __nv_bfloat16* __restrict__ W1l,
                         __nv_bfloat16* __restrict__ W2h, __nv_bfloat16* __restrict__ W2l)
{
    int i = blockIdx.x * 256 + threadIdx.x;
    __nv_bfloat16 hi, lo;
    if (i < 128 * 256) {
        split_bf16(W1[256 + i], hi, lo);   // skip row 0 (x weight)
        W1h[i] = hi; W1l[i] = lo;
    } else {
        int j = i - 128 * 256;
        split_bf16(W2[128 + j], hi, lo);   // skip row 0
        W2h[j] = hi; W2l[j] = lo;
    }
}

// ---------------------------------------------------------------------------
// XAGG precompute (runs once; not hot)
// ---------------------------------------------------------------------------
__global__ __launch_bounds__(256) void k_xagg(
    const float* __restrict__ X, const float* __restrict__ L, float* __restrict__ XAGG)
{
    __shared__ float As[16][64];
    __shared__ float Bs[16][64];
    const int tid = threadIdx.x;
    const int tx = tid & 15, ty = tid >> 4;
    const int r0 = blockIdx.y * 64;
    const int m0 = blockIdx.x * 64;

    float acc[4][4];
#pragma unroll
    for (int i = 0; i < 4; i++)
#pragma unroll
        for (int j = 0; j < 4; j++) acc[i][j] = 0.f;

    const int row = tid >> 2;
    const int kq  = (tid & 3) * 4;

    for (int k0 = 0; k0 < 512; k0 += 16) {
        float4 av = *reinterpret_cast<const float4*>(&X[(r0 + row) * 512 + k0 + kq]);
        As[kq + 0][row] = av.x; As[kq + 1][row] = av.y;
        As[kq + 2][row] = av.z; As[kq + 3][row] = av.w;
        float4 bv = *reinterpret_cast<const float4*>(&L[(m0 + row) * 512 + k0 + kq]);
        Bs[kq + 0][row] = bv.x; Bs[kq + 1][row] = bv.y;
        Bs[kq + 2][row] = bv.z; Bs[kq + 3][row] = bv.w;
        __syncthreads();
#pragma unroll
        for (int k = 0; k < 16; k++) {
            float4 a4 = *reinterpret_cast<const float4*>(&As[k][ty * 4]);
            float4 b4 = *reinterpret_cast<const float4*>(&Bs[k][tx * 4]);
            float a_[4] = {a4.x, a4.y, a4.z, a4.w};
            float b_[4] = {b4.x, b4.y, b4.z, b4.w};
#pragma unroll
            for (int i = 0; i < 4; i++)
#pragma unroll
                for (int j = 0; j < 4; j++)
                    acc[i][j] += a_[i] * b_[j];
        }
        __syncthreads();
    }
#pragma unroll
    for (int i = 0; i < 4; i++) {
        int bt = r0 + ty * 4 + i;
        int b = bt >> 6, tt = bt & 63;
#pragma unroll
        for (int j = 0; j < 4; j++)
            XAGG[tt * (BB * NB) + b * NB + m0 + tx * 4 + j] = acc[i][j];
    }
}

// ---------------------------------------------------------------------------
// Attention f,g + softmax beta per batch. grid 16, 256 thr.
// ---------------------------------------------------------------------------
__global__ void k_fg(const float* __restrict__ HS1,
                     const float* __restrict__ w2, const float* __restrict__ w3,
                     const float* __restrict__ b2p, const float* __restrict__ b3p,
                     float* __restrict__ BETA)
{
    __shared__ float sf[64], sg[64], st[64];
    const int b = blockIdx.x, tid = threadIdx.x;
    const int w = tid >> 5, lane = tid & 31;
    for (int t = w; t < 64; t += 8) {
        float fs = 0.f, gs = 0.f;
        for (int n = lane; n < 512; n += 32) {
            float v = HS1[b * (TT * NB) + t * NB + n];
            fs += v * w2[n];
            gs += v * w3[n];
        }
#pragma unroll
        for (int off = 16; off; off >>= 1) {
            fs += __shfl_down_sync(0xffffffffu, fs, off);
            gs += __shfl_down_sync(0xffffffffu, gs, off);
        }
        if (lane == 0) { sf[t] = fs + b2p[0]; sg[t] = gs + b3p[0]; }
    }
    __syncthreads();
    if (tid == 0) {
        float mx = -1e30f;
        for (int t = 0; t < 64; t++) { st[t] = sf[t] * sg[t]; mx = fmaxf(mx, st[t]); }
        float sum = 0.f;
        for (int t = 0; t < 64; t++) { st[t] = expf(st[t] - mx); sum += st[t]; }
        float inv = 1.f / sum;
        for (int t = 0; t < 64; t++) BETA[b * 64 + t] = st[t] * inv;
    }
}

// ---------------------------------------------------------------------------
// Output: out[b,p,n] = sum_t beta[b,t]*hs1[b,t,n]*W_out[t,p] + b_out[p]
// ---------------------------------------------------------------------------
__global__ void k_out(const float* __restrict__ HS1, const float* __restrict__ BETA,
                      const float* __restrict__ Wout, const float* __restrict__ bout,
                      float* __restrict__ out)
{
    const int idx = blockIdx.x * 256 + threadIdx.x;
    const int b = idx >> 9, n = idx & 511;
    float acc[PP];
#pragma unroll
    for (int p = 0; p < PP; p++) acc[p] = 0.f;
    for (int t = 0; t < 64; t++) {
        float v = BETA[b * 64 + t] * HS1[b * (TT * NB) + t * NB + n];
#pragma unroll
        for (int p = 0; p < PP; p++) acc[p] += v * Wout[t * PP + p];
    }
#pragma unroll
    for (int p = 0; p < PP; p++)
        out[b * (PP * NB) + p * NB + n] = acc[p] + bout[p];
}

// ---------------------------------------------------------------------------
extern "C" void kernel_launch(void* const* d_in, const int* in_sizes, int n_in,
                              void* d_out, int out_size)
{
    (void)in_sizes; (void)n_in; (void)out_size;
    const float* X    = (const float*)d_in[0];
    const float* L    = (const float*)d_in[1];
    const float* W1   = (const float*)d_in[2];
    const float* b1   = (const float*)d_in[3];
    const float* W2   = (const float*)d_in[4];
    const float* b2   = (const float*)d_in[5];
    const float* aw1  = (const float*)d_in[6];
    const float* aw2  = (const float*)d_in[7];
    const float* aw3  = (const float*)d_in[8];
    const float* ab1  = (const float*)d_in[9];
    const float* ab2  = (const float*)d_in[10];
    const float* ab3  = (const float*)d_in[11];
    const float* Wout = (const float*)d_in[12];
    const float* bout = (const float*)d_in[13];
    float* out = (float*)d_out;

    float *U, *XA, *HS1, *BETA;
    __nv_bfloat16 *Lh, *Ll, *Hh, *Hl, *RHh, *RHl, *AGGh, *AGGl;
    __nv_bfloat16 *W1hh, *W1hl, *W2hh, *W2hl;
    cudaGetSymbolAddress((void**)&U,    g_U);
    cudaGetSymbolAddress((void**)&XA,   g_XAGG);
    cudaGetSymbolAddress((void**)&HS1,  g_HS1);
    cudaGetSymbolAddress((void**)&BETA, g_BETA);
    cudaGetSymbolAddress((void**)&Lh,   g_Lh);
    cudaGetSymbolAddress((void**)&Ll,   g_Ll);
    cudaGetSymbolAddress((void**)&Hh,   g_Hh);
    cudaGetSymbolAddress((void**)&Hl,   g_Hl);
    cudaGetSymbolAddress((void**)&RHh,  g_RHh);
    cudaGetSymbolAddress((void**)&RHl,  g_RHl);
    cudaGetSymbolAddress((void**)&AGGh, g_AGGh);
    cudaGetSymbolAddress((void**)&AGGl, g_AGGl);
    cudaGetSymbolAddress((void**)&W1hh, g_W1hh);
    cudaGetSymbolAddress((void**)&W1hl, g_W1hl);
    cudaGetSymbolAddress((void**)&W2hh, g_W2hh);
    cudaGetSymbolAddress((void**)&W2hl, g_W2hl);

    cudaFuncSetAttribute(k_tmma,   cudaFuncAttributeMaxDynamicSharedMemorySize, SM_TMMA);
    cudaFuncSetAttribute(k_gate_t, cudaFuncAttributeMaxDynamicSharedMemorySize, SM_GC);
    cudaFuncSetAttribute(k_cand_t, cudaFuncAttributeMaxDynamicSharedMemorySize, SM_CAND);

    cudaMemsetAsync(Hh,   0, sizeof(__nv_bfloat16) * RWS * HH);
    cudaMemsetAsync(Hl,   0, sizeof(__nv_bfloat16) * RWS * HH);
    cudaMemsetAsync(AGGh, 0, sizeof(__nv_bfloat16) * RWS * HH);
    cudaMemsetAsync(AGGl, 0, sizeof(__nv_bfloat16) * RWS * HH);

    k_splitL<<<512, 512>>>(L, Lh, Ll);
    k_splitW<<<192, 256>>>(W1, W2, W1hh, W1hl, W2hh, W2hl);
    k_xagg<<<dim3(8, 16), 256>>>(X, L, XA);

    for (int t = 0; t < TT; t++) {
        if (t) k_tmma<<<dim3(32, 8), 256, SM_TMMA>>>(Lh, Ll, Hh, Hl, AGGh, AGGl);
        k_gate_t<<<dim3(2, 128), 256, SM_GC>>>(AGGh, AGGl, W1hh, W1hl, W1, b1,
                                               XA, t, Hh, Hl, RHh, RHl, U);
        if (t) k_tmma<<<dim3(32, 8), 256, SM_TMMA>>>(Lh, Ll, RHh, RHl, AGGh, AGGl);
        k_cand_t<<<dim3(1, 128), 256, SM_CAND>>>(AGGh, AGGl, W2hh, W2hl, W2, b2,
                                                 XA, t, aw1, ab1, U, Hh, Hl, HS1);
    }

    k_fg<<<16, 256>>>(HS1, aw2, aw3, ab2, ab3, BETA);
    k_out<<<32, 256>>>(HS1, BETA, Wout, bout, out);
}

// round 16
// speedup vs baseline: 1.2027x; 1.0046x over previous
#include <cuda_runtime.h>
#include <cuda_bf16.h>
#include <cstdint>

// Problem constants: B=16, T=64, N=512, H=128, P=12
#define NB   512
#define BB   16
#define TT   64
#define HH   128
#define PP   12
#define RWS  (NB*BB)          // 8192 rows (n,b)
#define BH   (BB*HH)          // 2048

// Scratch (device globals; no allocation allowed)
__device__ float g_U   [RWS*HH];          // update gate, h-layout
__device__ float g_XAGG[TT*BB*NB];        // [t][b][m] = (L @ x_t)[b,m]
__device__ float g_HS1 [BB*TT*NB];        // [b][t][n]
__device__ float g_BETA[BB*TT];
__device__ __nv_bfloat16 g_Lh  [NB*NB];   // L hi/lo (A of big GEMM)
__device__ __nv_bfloat16 g_Ll  [NB*NB];
__device__ __nv_bfloat16 g_Hh  [RWS*HH];  // H hi/lo
__device__ __nv_bfloat16 g_Hl  [RWS*HH];
__device__ __nv_bfloat16 g_RHh [RWS*HH];  // (r*h) hi/lo
__device__ __nv_bfloat16 g_RHl [RWS*HH];
__device__ __nv_bfloat16 g_AGGh[RWS*HH];  // L@B result hi/lo
__device__ __nv_bfloat16 g_AGGl[RWS*HH];
__device__ __nv_bfloat16 g_W1hh[HH*2*HH]; // W1 rows 1..128 hi/lo [128][256]
__device__ __nv_bfloat16 g_W1hl[HH*2*HH];
__device__ __nv_bfloat16 g_W2hh[HH*HH];   // W2 rows 1..128 hi/lo [128][128]
__device__ __nv_bfloat16 g_W2hl[HH*HH];

// ---------------------------------------------------------------------------
// Helpers
// ---------------------------------------------------------------------------
__device__ __forceinline__ uint32_t smem_to_u32(const void* p) {
    uint32_t a;
    asm("{ .reg .u64 t; cvta.to.shared.u64 t, %1; cvt.u32.u64 %0, t; }" : "=r"(a) : "l"(p));
    return a;
}
__device__ __forceinline__ void cp16(uint32_t saddr, const void* gaddr) {
    asm volatile("cp.async.cg.shared.global [%0], [%1], 16;" :: "r"(saddr), "l"(gaddr));
}
__device__ __forceinline__ void cp_commit() {
    asm volatile("cp.async.commit_group;" ::: "memory");
}
__device__ __forceinline__ void ldsm4(uint32_t r[4], uint32_t addr) {
    asm volatile("ldmatrix.sync.aligned.m8n8.x4.shared.b16 {%0,%1,%2,%3}, [%4];"
                 : "=r"(r[0]), "=r"(r[1]), "=r"(r[2]), "=r"(r[3]) : "r"(addr));
}
__device__ __forceinline__ void ldsm4t(uint32_t r[4], uint32_t addr) {
    asm volatile("ldmatrix.sync.aligned.m8n8.x4.trans.shared.b16 {%0,%1,%2,%3}, [%4];"
                 : "=r"(r[0]), "=r"(r[1]), "=r"(r[2]), "=r"(r[3]) : "r"(addr));
}
__device__ __forceinline__ void mma_bf16(float d[4], const uint32_t a[4],
                                         uint32_t b0, uint32_t b1) {
    asm volatile(
        "mma.sync.aligned.m16n8k16.row.col.f32.bf16.bf16.f32 "
        "{%0,%1,%2,%3}, {%4,%5,%6,%7}, {%8,%9}, {%0,%1,%2,%3};"
        : "+f"(d[0]), "+f"(d[1]), "+f"(d[2]), "+f"(d[3])
        : "r"(a[0]), "r"(a[1]), "r"(a[2]), "r"(a[3]), "r"(b0), "r"(b1));
}
__device__ __forceinline__ void split_bf16(float v, __nv_bfloat16& hi, __nv_bfloat16& lo) {
    hi = __float2bfloat16(v);
    lo = __float2bfloat16(v - __bfloat162float(hi));
}
__device__ __forceinline__ float sigmoid_fast(float x) {
    return __fdividef(1.f, 1.f + __expf(-x));
}
__device__ __forceinline__ float tanh_exp(float x) {
    // tanh(x) = 1 - 2/(e^{2x}+1); MUFU + fast div, few-ulp, stable both tails
    return 1.f - __fdividef(2.f, __expf(2.f * x) + 1.f);
}

// ---------------------------------------------------------------------------
// Big tensor GEMM: C[512][2048] = A[512,512] @ B[512,2048] via 3-pass bf16 split.
// CTA tile 64m x 64n, grid (32, 8) = 256 CTAs, 256 threads (8 warps = 4m x 2n).
// 32KB smem -> 2 CTAs resident per SM.
// ---------------------------------------------------------------------------
#define STAGE_BYTES 16384
#define OFF_AH 0
#define OFF_AL 4096
#define OFF_BH 8192
#define OFF_BL 12288
#define SM_TMMA (2*STAGE_BYTES)     // 32768

__global__ __launch_bounds__(256) void k_tmma(
    const __nv_bfloat16* __restrict__ Ah, const __nv_bfloat16* __restrict__ Al,
    const __nv_bfloat16* __restrict__ Bh, const __nv_bfloat16* __restrict__ Bl,
    __nv_bfloat16* __restrict__ Ch, __nv_bfloat16* __restrict__ Cl)
{
    extern __shared__ char smc[];
    const uint32_t sbase = smem_to_u32(smc);
    const int tid = threadIdx.x, wid = tid >> 5, lane = tid & 31;
    const int m0c = blockIdx.y * 64;
    const int n0c = blockIdx.x * 64;
    const int mw = (wid & 3) * 16;
    const int nw = (wid >> 2) * 32;

    float acc[4][4];
#pragma unroll
    for (int i = 0; i < 4; i++)
#pragma unroll
        for (int j = 0; j < 4; j++) acc[i][j] = 0.f;

    const int am = tid >> 2, aseg = tid & 3;
    const uint32_t aso = (uint32_t)(am * 64 + ((aseg ^ (am & 3)) << 4));
    const int bk0 = tid >> 3, bseg = tid & 7;
    const uint32_t bso = (uint32_t)(bk0 * 128 + ((bseg ^ (bk0 & 7)) << 4));

#define LOAD_STAGE(s) do {                                                         \
    const int kk = (s) * 32;                                                       \
    const uint32_t sb = sbase + ((s) & 1) * STAGE_BYTES;                           \
    cp16(sb + OFF_AH + aso, &Ah[(m0c + am) * 512 + kk + aseg * 8]);                \
    cp16(sb + OFF_AL + aso, &Al[(m0c + am) * 512 + kk + aseg * 8]);                \
    cp16(sb + OFF_BH + bso, &Bh[(kk + bk0) * 2048 + n0c + bseg * 8]);              \
    cp16(sb + OFF_BL + bso, &Bl[(kk + bk0) * 2048 + n0c + bseg * 8]);              \
    cp_commit();                                                                   \
} while (0)

    LOAD_STAGE(0);
    LOAD_STAGE(1);

    for (int s = 0; s < 16; s++) {
        if (s < 14) asm volatile("cp.async.wait_group 1;" ::: "memory");
        else        asm volatile("cp.async.wait_group 0;" ::: "memory");
        __syncthreads();

        const uint32_t sb = sbase + (s & 1) * STAGE_BYTES;
#pragma unroll
        for (int kh = 0; kh < 32; kh += 16) {
            uint32_t afh[4], afl[4];
            {
                const int row = mw + (lane & 15);
                const int seg = (kh >> 3) + (lane >> 4);
                const uint32_t ad = sb + OFF_AH + row * 64 + ((seg ^ (row & 3)) << 4);
                ldsm4(afh, ad);
                ldsm4(afl, ad + (OFF_AL - OFF_AH));
            }
            uint32_t bfh[2][4], bfl[2][4];
            {
                const int bk = kh + (lane & 15);
#pragma unroll
                for (int g = 0; g < 2; g++) {
                    const int seg = (nw >> 3) + 2 * g + (lane >> 4);
                    const uint32_t bd = sb + OFF_BH + bk * 128 + ((seg ^ (bk & 7)) << 4);
                    ldsm4t(bfh[g], bd);
                    ldsm4t(bfl[g], bd + (OFF_BL - OFF_BH));
                }
            }
#pragma unroll
            for (int nf = 0; nf < 4; nf++) {
                const int g = nf >> 1, h = (nf & 1) * 2;
                mma_bf16(acc[nf], afh, bfh[g][h], bfh[g][h + 1]);
                mma_bf16(acc[nf], afh, bfl[g][h], bfl[g][h + 1]);
                mma_bf16(acc[nf], afl, bfh[g][h], bfh[g][h + 1]);
            }
        }
        __syncthreads();
        if (s + 2 < 16) LOAD_STAGE(s + 2);
    }
#undef LOAD_STAGE

    const int r0 = m0c + mw + (lane >> 2);
    const int cb = n0c + nw + (lane & 3) * 2;
#pragma unroll
    for (int nf = 0; nf < 4; nf++) {
        const int col = cb + nf * 8;
#pragma unroll
        for (int half = 0; half < 2; half++) {
            const int r = r0 + half * 8;
            const int idx = r * BH + col;
            __nv_bfloat16 h0, l0, h1, l1;
            split_bf16(acc[nf][half * 2 + 0], h0, l0);
            split_bf16(acc[nf][half * 2 + 1], h1, l1);
            __nv_bfloat162 ph; ph.x = h0; ph.y = h1;
            __nv_bfloat162 pl; pl.x = l0; pl.y = l1;
            *reinterpret_cast<__nv_bfloat162*>(&Ch[idx]) = ph;
            *reinterpret_cast<__nv_bfloat162*>(&Cl[idx]) = pl;
        }
    }
}

// ---------------------------------------------------------------------------
// Shared K=128 HMMA core for gate: A[64 rows x 128] (hi/lo) @ W[128 x 128]
// (hi/lo), 3-pass. 256 threads, 8 warps (4m x 2n). All tiles single-shot in smem.
// smem layout (dynamic): AH 0 (16KB), AL 16384, WH 32768 (32KB), WL 65536 -> 96KB
// ---------------------------------------------------------------------------
#define SM_GC 98304

template<int LDW>
__device__ __forceinline__ void hmma_k128(
    const __nv_bfloat16* __restrict__ Ah_g,  // &A[r0c*128]
    const __nv_bfloat16* __restrict__ Al_g,
    const __nv_bfloat16* __restrict__ Wh_g,  // &W[o0], row stride LDW
    const __nv_bfloat16* __restrict__ Wl_g,
    uint32_t sbase, float acc[8][4], int mw, int nw, int lane, int tid)
{
#pragma unroll
    for (int u = 0; u < 4; u++) {
        const int unit = tid + u * 256;
        const int row = unit >> 4, seg = unit & 15;
        const uint32_t so = (uint32_t)(row * 256 + ((seg ^ (row & 7)) << 4));
        cp16(sbase + 0     + so, Ah_g + row * 128 + seg * 8);
        cp16(sbase + 16384 + so, Al_g + row * 128 + seg * 8);
    }
#pragma unroll
    for (int u = 0; u < 8; u++) {
        const int unit = tid + u * 256;
        const int k = unit >> 4, seg = unit & 15;
        const uint32_t so = (uint32_t)(k * 256 + ((seg ^ (k & 7)) << 4));
        cp16(sbase + 32768 + so, Wh_g + k * LDW + seg * 8);
        cp16(sbase + 65536 + so, Wl_g + k * LDW + seg * 8);
    }
    cp_commit();
    asm volatile("cp.async.wait_group 0;" ::: "memory");
    __syncthreads();

#pragma unroll
    for (int kh = 0; kh < 8; kh++) {
        uint32_t afh[4], afl[4];
        {
            const int row = mw + (lane & 15);
            const int seg = kh * 2 + (lane >> 4);
            const uint32_t ao = (uint32_t)(row * 256 + ((seg ^ (row & 7)) << 4));
            ldsm4(afh, sbase + ao);
            ldsm4(afl, sbase + 16384 + ao);
        }
        uint32_t bfh[4][4], bfl[4][4];
        {
            const int bk = kh * 16 + (lane & 15);
#pragma unroll
            for (int g = 0; g < 4; g++) {
                const int seg = (nw >> 3) + 2 * g + (lane >> 4);
                const uint32_t wo = (uint32_t)(bk * 256 + ((seg ^ (bk & 7)) << 4));
                ldsm4t(bfh[g], sbase + 32768 + wo);
                ldsm4t(bfl[g], sbase + 65536 + wo);
            }
        }
#pragma unroll
        for (int nf = 0; nf < 8; nf++) {
            const int g = nf >> 1, h = (nf & 1) * 2;
            mma_bf16(acc[nf], afh, bfh[g][h], bfh[g][h + 1]);
            mma_bf16(acc[nf], afh, bfl[g][h], bfl[g][h + 1]);
            mma_bf16(acc[nf], afl, bfh[g][h], bfh[g][h + 1]);
        }
    }
}

// ---------------------------------------------------------------------------
// Gate (tensorized, H register-prefetch): sigmoid(AGG @ W1h + xagg*W1x + b1)
// r-half -> RH = r*h (bf16 split), u-half -> U (fp32, h-layout).
// isR is uniform per CTA (r0c<4096); r-CTAs issue their 32 Hh/Hl loads into
// registers BEFORE the MMA phase so the latency hides under load+compute.
// grid (2 o-tiles, 128 r-tiles), 256 threads.
// ---------------------------------------------------------------------------
__global__ __launch_bounds__(256) void k_gate_t(
    const __nv_bfloat16* __restrict__ AGGh, const __nv_bfloat16* __restrict__ AGGl,
    const __nv_bfloat16* __restrict__ W1hh, const __nv_bfloat16* __restrict__ W1hl,
    const float* __restrict__ W1, const float* __restrict__ b1,
    const float* __restrict__ Xagg, int t,
    const __nv_bfloat16* __restrict__ Hh, const __nv_bfloat16* __restrict__ Hl,
    __nv_bfloat16* __restrict__ RHh, __nv_bfloat16* __restrict__ RHl,
    float* __restrict__ U)
{
    extern __shared__ char smc[];
    const uint32_t sbase = smem_to_u32(smc);
    const int tid = threadIdx.x, wid = tid >> 5, lane = tid & 31;
    const int mw = (wid & 3) * 16, nw = (wid >> 2) * 64;
    const int r0c = blockIdx.y * 64;
    const int o0 = blockIdx.x * 128;
    const int bit = blockIdx.x;
    const bool isR = (r0c < 4096);          // uniform per CTA
    const int rr0 = r0c + mw + (lane >> 2);

    // Register prefetch of H operands for the r-half epilogue.
    __nv_bfloat162 pHh[2][8], pHl[2][8];
    if (isR) {
#pragma unroll
        for (int half = 0; half < 2; half++) {
            const int r = rr0 + half * 8;
            const int mq = r >> 4, b = r & 15;
            const int nbase = 2 * mq + bit;
#pragma unroll
            for (int nf = 0; nf < 8; nf++) {
                const int o = o0 + nw + (lane & 3) * 2 + nf * 8;
                const int c = o & 127;
                const int idx = (nbase * 16 + b) * 128 + c;
                pHh[half][nf] = __ldg(reinterpret_cast<const __nv_bfloat162*>(&Hh[idx]));
                pHl[half][nf] = __ldg(reinterpret_cast<const __nv_bfloat162*>(&Hl[idx]));
            }
        }
    }

    float acc[8][4];
#pragma unroll
    for (int i = 0; i < 8; i++)
#pragma unroll
        for (int j = 0; j < 4; j++) acc[i][j] = 0.f;

    hmma_k128<256>(AGGh + r0c * 128, AGGl + r0c * 128, W1hh + o0, W1hl + o0,
                   sbase, acc, mw, nw, lane, tid);

#pragma unroll
    for (int half = 0; half < 2; half++) {
        const int r = rr0 + half * 8;
        const int mq = r >> 4, b = r & 15;
        const float xa = Xagg[t * (BB * NB) + b * NB + mq];
        const int nbase = isR ? (2 * mq + bit) : (2 * (mq - 256) + bit);
#pragma unroll
        for (int nf = 0; nf < 8; nf++) {
            const int o = o0 + nw + (lane & 3) * 2 + nf * 8;
            const float v0 = acc[nf][half * 2 + 0] + xa * W1[o]     + b1[o];
            const float v1 = acc[nf][half * 2 + 1] + xa * W1[o + 1] + b1[o + 1];
            const float s0 = sigmoid_fast(v0);
            const float s1 = sigmoid_fast(v1);
            const int c = o & 127;
            const int idx = (nbase * 16 + b) * 128 + c;
            if (isR) {
                const __nv_bfloat162 hh = pHh[half][nf];
                const __nv_bfloat162 hl = pHl[half][nf];
                const float h0 = __bfloat162float(hh.x) + __bfloat162float(hl.x);
                const float h1 = __bfloat162float(hh.y) + __bfloat162float(hl.y);
                const float rh0 = s0 * h0, rh1 = s1 * h1;
                __nv_bfloat16 a0, c0, a1, c1;
                split_bf16(rh0, a0, c0);
                split_bf16(rh1, a1, c1);
                __nv_bfloat162 ph; ph.x = a0; ph.y = a1;
                __nv_bfloat162 pl; pl.x = c0; pl.y = c1;
                *reinterpret_cast<__nv_bfloat162*>(&RHh[idx]) = ph;
                *reinterpret_cast<__nv_bfloat162*>(&RHl[idx]) = pl;
            } else {
                *reinterpret_cast<float2*>(&U[idx]) = make_float2(s0, s1);
            }
        }
    }
}

// ---------------------------------------------------------------------------
// Candidate (tensorized, epilogue-prefetched): C = tanh(AGG2@W2h + xagg*W2x + b2);
// h_new = u*h + (1-u)*C; write Hh/Hl; fused hs1 row-reduction.
// U / Hh / Hl tiles prefetched into smem with A and W (epilogue reads = LDS).
// smem: AH 0, AL 16K, WH 32K, WL 64K, U 96K(32K), sHh 128K(16K), sHl 144K -> 160KB
// grid (1, 128), 256 threads.
// ---------------------------------------------------------------------------
#define SM_CAND 163840
#define CU_OFF  98304
#define CHH_OFF 131072
#define CHL_OFF 147456

__global__ __launch_bounds__(256) void k_cand_t(
    const __nv_bfloat16* __restrict__ AGGh, const __nv_bfloat16* __restrict__ AGGl,
    const __nv_bfloat16* __restrict__ W2hh, const __nv_bfloat16* __restrict__ W2hl,
    const float* __restrict__ W2, const float* __restrict__ b2,
    const float* __restrict__ Xagg, int t,
    const float* __restrict__ aw1, const float* __restrict__ ab1,
    const float* __restrict__ U,
    __nv_bfloat16* __restrict__ Hh, __nv_bfloat16* __restrict__ Hl,
    float* __restrict__ HS1)
{
    extern __shared__ char smc[];
    __shared__ float sRed[64];
    const uint32_t sbase = smem_to_u32(smc);
    const int tid = threadIdx.x, wid = tid >> 5, lane = tid & 31;
    const int mw = (wid & 3) * 16, nw = (wid >> 2) * 64;
    const int r0c = blockIdx.y * 64;

    // A tile (64 x 128 hi/lo, swizzled)
#pragma unroll
    for (int u = 0; u < 4; u++) {
        const int unit = tid + u * 256;
        const int row = unit >> 4, seg = unit & 15;
        const uint32_t so = (uint32_t)(row * 256 + ((seg ^ (row & 7)) << 4));
        cp16(sbase + 0     + so, AGGh + (r0c + row) * 128 + seg * 8);
        cp16(sbase + 16384 + so, AGGl + (r0c + row) * 128 + seg * 8);
    }
    // W2 (128 x 128 hi/lo, swizzled)
#pragma unroll
    for (int u = 0; u < 8; u++) {
        const int unit = tid + u * 256;
        const int k = unit >> 4, seg = unit & 15;
        const uint32_t so = (uint32_t)(k * 256 + ((seg ^ (k & 7)) << 4));
        cp16(sbase + 32768 + so, W2hh + k * 128 + seg * 8);
        cp16(sbase + 65536 + so, W2hl + k * 128 + seg * 8);
    }
    // Epilogue operand prefetch: U (64 rows x 512B), Hh/Hl (64 rows x 256B), linear
#pragma unroll
    for (int u = 0; u < 8; u++) {
        const int unit = tid + u * 256;            // 2048 16B-chunks
        const int row = unit >> 5, seg = unit & 31;
        cp16(sbase + CU_OFF + row * 512 + seg * 16, U + (r0c + row) * 128 + seg * 4);
    }
#pragma unroll
    for (int u = 0; u < 4; u++) {
        const int unit = tid + u * 256;            // 1024 16B-chunks
        const int row = unit >> 4, seg = unit & 15;
        cp16(sbase + CHH_OFF + row * 256 + seg * 16, Hh + (r0c + row) * 128 + seg * 8);
        cp16(sbase + CHL_OFF + row * 256 + seg * 16, Hl + (r0c + row) * 128 + seg * 8);
    }
    cp_commit();
    asm volatile("cp.async.wait_group 0;" ::: "memory");
    __syncthreads();

    float acc[8][4];
#pragma unroll
    for (int i = 0; i < 8; i++)
#pragma unroll
        for (int j = 0; j < 4; j++) acc[i][j] = 0.f;

#pragma unroll
    for (int kh = 0; kh < 8; kh++) {
        uint32_t afh[4], afl[4];
        {
            const int row = mw + (lane & 15);
            const int seg = kh * 2 + (lane >> 4);
            const uint32_t ao = (uint32_t)(row * 256 + ((seg ^ (row & 7)) << 4));
            ldsm4(afh, sbase + ao);
            ldsm4(afl, sbase + 16384 + ao);
        }
        uint32_t bfh[4][4], bfl[4][4];
        {
            const int bk = kh * 16 + (lane & 15);
#pragma unroll
            for (int g = 0; g < 4; g++) {
                const int seg = (nw >> 3) + 2 * g + (lane >> 4);
                const uint32_t wo = (uint32_t)(bk * 256 + ((seg ^ (bk & 7)) << 4));
                ldsm4t(bfh[g], sbase + 32768 + wo);
                ldsm4t(bfl[g], sbase + 65536 + wo);
            }
        }
#pragma unroll
        for (int nf = 0; nf < 8; nf++) {
            const int g = nf >> 1, h = (nf & 1) * 2;
            mma_bf16(acc[nf], afh, bfh[g][h], bfh[g][h + 1]);
            mma_bf16(acc[nf], afh, bfl[g][h], bfl[g][h + 1]);
            mma_bf16(acc[nf], afl, bfh[g][h], bfh[g][h + 1]);
        }
    }

    const int rr0 = r0c + mw + (lane >> 2);
    float part[2] = {0.f, 0.f};
#pragma unroll
    for (int half = 0; half < 2; half++) {
        const int r = rr0 + half * 8;
        const int lr = r - r0c;
        const int mq = r >> 4, b = r & 15;
        const float xa = Xagg[t * (BB * NB) + b * NB + mq];
#pragma unroll
        for (int nf = 0; nf < 8; nf++) {
            const int o = nw + (lane & 3) * 2 + nf * 8;
            const float pre0 = acc[nf][half * 2 + 0] + xa * W2[o]     + b2[o];
            const float pre1 = acc[nf][half * 2 + 1] + xa * W2[o + 1] + b2[o + 1];
            const float cv0 = tanh_exp(pre0);
            const float cv1 = tanh_exp(pre1);
            const float2 uu = *reinterpret_cast<const float2*>(smc + CU_OFF + lr * 512 + o * 4);
            __nv_bfloat162 hh = *reinterpret_cast<const __nv_bfloat162*>(smc + CHH_OFF + lr * 256 + o * 2);
            __nv_bfloat162 hl = *reinterpret_cast<const __nv_bfloat162*>(smc + CHL_OFF + lr * 256 + o * 2);
            const float h0 = __bfloat162float(hh.x) + __bfloat162float(hl.x);
            const float h1 = __bfloat162float(hh.y) + __bfloat162float(hl.y);
            const float hn0 = uu.x * h0 + (1.f - uu.x) * cv0;
            const float hn1 = uu.y * h1 + (1.f - uu.y) * cv1;
            const int idx = r * 128 + o;
            __nv_bfloat16 a0, c0, a1, c1;
            split_bf16(hn0, a0, c0);
            split_bf16(hn1, a1, c1);
            __nv_bfloat162 ph; ph.x = a0; ph.y = a1;
            __nv_bfloat162 pl; pl.x = c0; pl.y = c1;
            *reinterpret_cast<__nv_bfloat162*>(&Hh[idx]) = ph;
            *reinterpret_cast<__nv_bfloat162*>(&Hl[idx]) = pl;
            part[half] += hn0 * aw1[o] + hn1 * aw1[o + 1];
        }
    }
    // reduce over the 4 lanes of each quad (same row)
#pragma unroll
    for (int half = 0; half < 2; half++) {
        part[half] += __shfl_xor_sync(0xffffffffu, part[half], 1);
        part[half] += __shfl_xor_sync(0xffffffffu, part[half], 2);
    }
    if (wid >= 4 && (lane & 3) == 0) {
        sRed[mw + (lane >> 2)]     = part[0];
        sRed[mw + 8 + (lane >> 2)] = part[1];
    }
    __syncthreads();
    if (wid < 4 && (lane & 3) == 0) {
        const float abv = ab1[0];
#pragma unroll
        for (int half = 0; half < 2; half++) {
            const int lr = mw + half * 8 + (lane >> 2);
            const int r = r0c + lr;
            const int mq = r >> 4, b = r & 15;
            HS1[b * (TT * NB) + t * NB + mq] = part[half] + sRed[lr] + abv;
        }
    }
}

// ---------------------------------------------------------------------------
// One-time splits
// ---------------------------------------------------------------------------
__global__ void k_splitL(const float* __restrict__ L,
                         __nv_bfloat16* __restrict__ Lh, __nv_bfloat16* __restrict__ Ll)
{
    int i = blockIdx.x * 512 + threadIdx.x;
    __nv_bfloat16 hi, lo;
    split_bf16(L[i], hi, lo);
    Lh[i] = hi; Ll[i] = lo;
}

__global__ void k_splitW(const float* __restrict__ W1, const float* __restrict__ W2,
                         __nv_bfloat16* __restrict__ W1h, __nv_bfloat16* __restrict__ W1l,
                         __nv_bfloat16* __restrict__ W2h, __nv_bfloat16* __restrict__ W2l)
{
    int i = blockIdx.x * 256 + threadIdx.x;
    __nv_bfloat16 hi, lo;
    if (i < 128 * 256) {
        split_bf16(W1[256 + i], hi, lo);   // skip row 0 (x weight)
        W1h[i] = hi; W1l[i] = lo;
    } else {
        int j = i - 128 * 256;
        split_bf16(W2[128 + j], hi, lo);   // skip row 0
        W2h[j] = hi; W2l[j] = lo;
    }
}

// ---------------------------------------------------------------------------
// XAGG precompute (runs once; not hot)
// ---------------------------------------------------------------------------
__global__ __launch_bounds__(256) void k_xagg(
    const float* __restrict__ X, const float* __restrict__ L, float* __restrict__ XAGG)
{
    __shared__ float As[16][64];
    __shared__ float Bs[16][64];
    const int tid = threadIdx.x;
    const int tx = tid & 15, ty = tid >> 4;
    const int r0 = blockIdx.y * 64;
    const int m0 = blockIdx.x * 64;

    float acc[4][4];
#pragma unroll
    for (int i = 0; i < 4; i++)
#pragma unroll
        for (int j = 0; j < 4; j++) acc[i][j] = 0.f;

    const int row = tid >> 2;
    const int kq  = (tid & 3) * 4;

    for (int k0 = 0; k0 < 512; k0 += 16) {
        float4 av = *reinterpret_cast<const float4*>(&X[(r0 + row) * 512 + k0 + kq]);
        As[kq + 0][row] = av.x; As[kq + 1][row] = av.y;
        As[kq + 2][row] = av.z; As[kq + 3][row] = av.w;
        float4 bv = *reinterpret_cast<const float4*>(&L[(m0 + row) * 512 + k0 + kq]);
        Bs[kq + 0][row] = bv.x; Bs[kq + 1][row] = bv.y;
        Bs[kq + 2][row] = bv.z; Bs[kq + 3][row] = bv.w;
        __syncthreads();
#pragma unroll
        for (int k = 0; k < 16; k++) {
            float4 a4 = *reinterpret_cast<const float4*>(&As[k][ty * 4]);
            float4 b4 = *reinterpret_cast<const float4*>(&Bs[k][tx * 4]);
            float a_[4] = {a4.x, a4.y, a4.z, a4.w};
            float b_[4] = {b4.x, b4.y, b4.z, b4.w};
#pragma unroll
            for (int i = 0; i < 4; i++)
#pragma unroll
                for (int j = 0; j < 4; j++)
                    acc[i][j] += a_[i] * b_[j];
        }
        __syncthreads();
    }
#pragma unroll
    for (int i = 0; i < 4; i++) {
        int bt = r0 + ty * 4 + i;
        int b = bt >> 6, tt = bt & 63;
#pragma unroll
        for (int j = 0; j < 4; j++)
            XAGG[tt * (BB * NB) + b * NB + m0 + tx * 4 + j] = acc[i][j];
    }
}

// ---------------------------------------------------------------------------
// Attention f,g + softmax beta per batch. grid 16, 256 thr.
// ---------------------------------------------------------------------------
__global__ void k_fg(const float* __restrict__ HS1,
                     const float* __restrict__ w2, const float* __restrict__ w3,
                     const float* __restrict__ b2p, const float* __restrict__ b3p,
                     float* __restrict__ BETA)
{
    __shared__ float sf[64], sg[64], st[64];
    const int b = blockIdx.x, tid = threadIdx.x;
    const int w = tid >> 5, lane = tid & 31;
    for (int t = w; t < 64; t += 8) {
        float fs = 0.f, gs = 0.f;
        for (int n = lane; n < 512; n += 32) {
            float v = HS1[b * (TT * NB) + t * NB + n];
            fs += v * w2[n];
            gs += v * w3[n];
        }
#pragma unroll
        for (int off = 16; off; off >>= 1) {
            fs += __shfl_down_sync(0xffffffffu, fs, off);
            gs += __shfl_down_sync(0xffffffffu, gs, off);
        }
        if (lane == 0) { sf[t] = fs + b2p[0]; sg[t] = gs + b3p[0]; }
    }
    __syncthreads();
    if (tid == 0) {
        float mx = -1e30f;
        for (int t = 0; t < 64; t++) { st[t] = sf[t] * sg[t]; mx = fmaxf(mx, st[t]); }
        float sum = 0.f;
        for (int t = 0; t < 64; t++) { st[t] = expf(st[t] - mx); sum += st[t]; }
        float inv = 1.f / sum;
        for (int t = 0; t < 64; t++) BETA[b * 64 + t] = st[t] * inv;
    }
}

// ---------------------------------------------------------------------------
// Output: out[b,p,n] = sum_t beta[b,t]*hs1[b,t,n]*W_out[t,p] + b_out[p]
// ---------------------------------------------------------------------------
__global__ void k_out(const float* __restrict__ HS1, const float* __restrict__ BETA,
                      const float* __restrict__ Wout, const float* __restrict__ bout,
                      float* __restrict__ out)
{
    const int idx = blockIdx.x * 256 + threadIdx.x;
    const int b = idx >> 9, n = idx & 511;
    float acc[PP];
#pragma unroll
    for (int p = 0; p < PP; p++) acc[p] = 0.f;
    for (int t = 0; t < 64; t++) {
        float v = BETA[b * 64 + t] * HS1[b * (TT * NB) + t * NB + n];
#pragma unroll
        for (int p = 0; p < PP; p++) acc[p] += v * Wout[t * PP + p];
    }
#pragma unroll
    for (int p = 0; p < PP; p++)
        out[b * (PP * NB) + p * NB + n] = acc[p] + bout[p];
}

// ---------------------------------------------------------------------------
extern "C" void kernel_launch(void* const* d_in, const int* in_sizes, int n_in,
                              void* d_out, int out_size)
{
    (void)in_sizes; (void)n_in; (void)out_size;
    const float* X    = (const float*)d_in[0];
    const float* L    = (const float*)d_in[1];
    const float* W1   = (const float*)d_in[2];
    const float* b1   = (const float*)d_in[3];
    const float* W2   = (const float*)d_in[4];
    const float* b2   = (const float*)d_in[5];
    const float* aw1  = (const float*)d_in[6];
    const float* aw2  = (const float*)d_in[7];
    const float* aw3  = (const float*)d_in[8];
    const float* ab1  = (const float*)d_in[9];
    const float* ab2  = (const float*)d_in[10];
    const float* ab3  = (const float*)d_in[11];
    const float* Wout = (const float*)d_in[12];
    const float* bout = (const float*)d_in[13];
    float* out = (float*)d_out;

    float *U, *XA, *HS1, *BETA;
    __nv_bfloat16 *Lh, *Ll, *Hh, *Hl, *RHh, *RHl, *AGGh, *AGGl;
    __nv_bfloat16 *W1hh, *W1hl, *W2hh, *W2hl;
    cudaGetSymbolAddress((void**)&U,    g_U);
    cudaGetSymbolAddress((void**)&XA,   g_XAGG);
    cudaGetSymbolAddress((void**)&HS1,  g_HS1);
    cudaGetSymbolAddress((void**)&BETA, g_BETA);
    cudaGetSymbolAddress((void**)&Lh,   g_Lh);
    cudaGetSymbolAddress((void**)&Ll,   g_Ll);
    cudaGetSymbolAddress((void**)&Hh,   g_Hh);
    cudaGetSymbolAddress((void**)&Hl,   g_Hl);
    cudaGetSymbolAddress((void**)&RHh,  g_RHh);
    cudaGetSymbolAddress((void**)&RHl,  g_RHl);
    cudaGetSymbolAddress((void**)&AGGh, g_AGGh);
    cudaGetSymbolAddress((void**)&AGGl, g_AGGl);
    cudaGetSymbolAddress((void**)&W1hh, g_W1hh);
    cudaGetSymbolAddress((void**)&W1hl, g_W1hl);
    cudaGetSymbolAddress((void**)&W2hh, g_W2hh);
    cudaGetSymbolAddress((void**)&W2hl, g_W2hl);

    cudaFuncSetAttribute(k_tmma,   cudaFuncAttributeMaxDynamicSharedMemorySize, SM_TMMA);
    cudaFuncSetAttribute(k_gate_t, cudaFuncAttributeMaxDynamicSharedMemorySize, SM_GC);
    cudaFuncSetAttribute(k_cand_t, cudaFuncAttributeMaxDynamicSharedMemorySize, SM_CAND);

    cudaMemsetAsync(Hh,   0, sizeof(__nv_bfloat16) * RWS * HH);
    cudaMemsetAsync(Hl,   0, sizeof(__nv_bfloat16) * RWS * HH);
    cudaMemsetAsync(AGGh, 0, sizeof(__nv_bfloat16) * RWS * HH);
    cudaMemsetAsync(AGGl, 0, sizeof(__nv_bfloat16) * RWS * HH);

    k_splitL<<<512, 512>>>(L, Lh, Ll);
    k_splitW<<<192, 256>>>(W1, W2, W1hh, W1hl, W2hh, W2hl);
    k_xagg<<<dim3(8, 16), 256>>>(X, L, XA);

    for (int t = 0; t < TT; t++) {
        if (t) k_tmma<<<dim3(32, 8), 256, SM_TMMA>>>(Lh, Ll, Hh, Hl, AGGh, AGGl);
        k_gate_t<<<dim3(2, 128), 256, SM_GC>>>(AGGh, AGGl, W1hh, W1hl, W1, b1,
                                               XA, t, Hh, Hl, RHh, RHl, U);
        if (t) k_tmma<<<dim3(32, 8), 256, SM_TMMA>>>(Lh, Ll, RHh, RHl, AGGh, AGGl);
        k_cand_t<<<dim3(1, 128), 256, SM_CAND>>>(AGGh, AGGl, W2hh, W2hl, W2, b2,
                                                 XA, t, aw1, ab1, U, Hh, Hl, HS1);
    }

    k_fg<<<16, 256>>>(HS1, aw2, aw3, ab2, ab3, BETA);
    k_out<<<32, 256>>>(HS1, BETA, Wout, bout, out);
}